// round 11
// baseline (speedup 1.0000x reference)
#include <cuda_runtime.h>
#include <cuda_fp16.h>
#include <cuda_bf16.h>
#include <cstdint>

// Problem dims
#define NB   16384
#define NF   1024
#define NH   64
#define ND   256
#define BD   (NB * ND)

// ---------------------------------------------------------------------------
// Scratch (device globals — no allocations allowed)
// ---------------------------------------------------------------------------
__device__ float g_hid[3ull * NB * 256];    // per-group hidden [B, 256], relu'd
__device__ float g_gates[(size_t)NB * 28];  // per row: gA[8] | gS[12] | gB[8]

extern __shared__ char dynsm[];

// ---------------------------------------------------------------------------
// Helpers
// ---------------------------------------------------------------------------
__device__ __forceinline__ uint32_t h2pack(float a, float b) {
    __half2 h = __floats2half2_rn(a, b);
    return *(uint32_t*)&h;
}

// m16n8k16 fp16 MMA, fp32 accumulate — NATIVE HMMA on sm_103 (sm_80 PTX)
#define MMA_F16(c, a, b) \
    asm("mma.sync.aligned.m16n8k16.row.col.f32.f16.f16.f32 " \
        "{%0,%1,%2,%3}, {%4,%5,%6,%7}, {%8,%9}, {%0,%1,%2,%3};" \
        : "+f"((c)[0]), "+f"((c)[1]), "+f"((c)[2]), "+f"((c)[3]) \
        : "r"((a)[0]), "r"((a)[1]), "r"((a)[2]), "r"((a)[3]), \
          "r"((b)[0]), "r"((b)[1]))

// Packed f32x2 helpers (combine kernel)
#define FMA2(acc, a, b) asm("fma.rn.f32x2 %0, %1, %2, %0;" : "+l"(acc) : "l"(a), "l"(b))
#define PACK2(dst, lo, hi) asm("mov.b64 %0, {%1, %2};" : "=l"(dst) : "r"(lo), "r"(hi))
#define UNPACK2(lo, hi, v) asm("mov.b64 {%0, %1}, %2;" : "=r"(lo), "=r"(hi) : "l"(v))

// ---------------------------------------------------------------------------
// Kernel 1: layer-1 via native fp16 mma.sync (m16n8k16). CTA tile 128x128,
// K-chunk 16, 2-stage double buffer, one sync per chunk.
// 8 warps as 4(m) x 2(n); warp tile 32x64 = 2 m-atoms x 8 n-atoms.
//   C[b, e*64+h] = relu( sum_f x[b,f] * W1[e,f,h] + b1[e,h] )
// A smem: [row][k2] half2, stride 9 (uint32). Reads ~conflict-free.
// B smem: [n][k2] half2, stride 9, k2 XOR-swizzled by (n>>3)&7 so the
//         transpose STS is <=2-way and reads stay conflict-free.
// ---------------------------------------------------------------------------
struct G1Args { const float* x[3]; const float* W1[3]; const float* b1[3]; };

#define ASTR 9

__global__ __launch_bounds__(256) void gemm1_kernel(G1Args args) {
    __shared__ uint32_t As[2][128 * ASTR];
    __shared__ uint32_t Bsm[2][128 * ASTR];
    __shared__ float bias_s[256];

    const int t = threadIdx.x, lane = t & 31, w = t >> 5;
    const int wm = w >> 1, wn = w & 1;       // warp grid 4x2
    const int g = lane >> 2, tt = lane & 3;  // fragment coords
    const int row0 = blockIdx.x * 128;
    const int n0   = blockIdx.y * 128;
    const int grp  = blockIdx.z;
    const float* __restrict__ x  = args.x[grp];
    const float* __restrict__ W1 = args.W1[grp];

    bias_s[t] = args.b1[grp][t];

    // staging roles: t<128 stage A (one x-row each); t>=128 stage B
    const bool isA = t < 128;
    const int ar  = t;                       // A row (t<128)
    const int u   = t - 128;                 // B thread id
    const int kp  = u >> 4;                  // k-pair 0..7 (f rows 2kp,2kp+1)
    const int n0b = (u & 15) * 8;            // local n base 0..120
    const int be  = (n0 + n0b) >> 6;         // expert
    const int bh  = (n0 + n0b) & 63;
    const int bswz = (u & 15) & 7;           // (n_local>>3)&7 for this thread

    const float* xg = x + (size_t)(row0 + ar) * NF;
    const float* wb = W1 + (size_t)be * NF * NH + bh;

    float acc[2][8][4];
    #pragma unroll
    for (int ma = 0; ma < 2; ma++)
        #pragma unroll
        for (int na = 0; na < 8; na++)
            #pragma unroll
            for (int i = 0; i < 4; i++) acc[ma][na][i] = 0.f;

    float rbuf[16];

    auto ldg = [&](int c) {
        if (isA) {
            const float* p = xg + c * 16;
            *(float4*)&rbuf[0]  = *(const float4*)(p);
            *(float4*)&rbuf[4]  = *(const float4*)(p + 4);
            *(float4*)&rbuf[8]  = *(const float4*)(p + 8);
            *(float4*)&rbuf[12] = *(const float4*)(p + 12);
        } else {
            const float* p0 = wb + (size_t)(c * 16 + 2 * kp) * NH;
            const float* p1 = p0 + NH;
            *(float4*)&rbuf[0]  = *(const float4*)(p0);
            *(float4*)&rbuf[4]  = *(const float4*)(p0 + 4);
            *(float4*)&rbuf[8]  = *(const float4*)(p1);
            *(float4*)&rbuf[12] = *(const float4*)(p1 + 4);
        }
    };
    auto sts = [&](int s) {
        if (isA) {
            #pragma unroll
            for (int j = 0; j < 8; j++)
                As[s][ar * ASTR + j] = h2pack(rbuf[2 * j], rbuf[2 * j + 1]);
        } else {
            #pragma unroll
            for (int j = 0; j < 8; j++)
                Bsm[s][(n0b + j) * ASTR + (kp ^ bswz)] = h2pack(rbuf[j], rbuf[8 + j]);
        }
    };

    ldg(0);
    sts(0);
    ldg(1);
    __syncthreads();

    for (int c = 0; c < 64; c++) {
        const int s = c & 1;
        if (c + 1 < 64) sts((c + 1) & 1);
        if (c + 2 < 64) ldg(c + 2);

        uint32_t af[2][4];
        #pragma unroll
        for (int ma = 0; ma < 2; ma++) {
            const int mr = wm * 32 + ma * 16;
            af[ma][0] = As[s][(mr + g) * ASTR + tt];
            af[ma][1] = As[s][(mr + g + 8) * ASTR + tt];
            af[ma][2] = As[s][(mr + g) * ASTR + tt + 4];
            af[ma][3] = As[s][(mr + g + 8) * ASTR + tt + 4];
        }
        #pragma unroll
        for (int na = 0; na < 8; na++) {
            const int nl = wn * 64 + na * 8 + g;
            const int sx = (wn * 8 + na) & 7;
            uint32_t bf[2];
            bf[0] = Bsm[s][nl * ASTR + (tt ^ sx)];
            bf[1] = Bsm[s][nl * ASTR + ((tt + 4) ^ sx)];
            MMA_F16(acc[0][na], af[0], bf);
            MMA_F16(acc[1][na], af[1], bf);
        }
        __syncthreads();
    }

    // epilogue: bias + relu, float2 stores (bias indexed by GLOBAL column)
    float* hb = g_hid + (size_t)grp * NB * 256;
    #pragma unroll
    for (int ma = 0; ma < 2; ma++) {
        const int r_ = row0 + wm * 32 + ma * 16 + g;
        #pragma unroll
        for (int na = 0; na < 8; na++) {
            const int colb = wn * 64 + na * 8 + 2 * tt;
            const float bb0 = bias_s[n0 + colb];
            const float bb1 = bias_s[n0 + colb + 1];
            float2 v0, v1;
            v0.x = fmaxf(acc[ma][na][0] + bb0, 0.f);
            v0.y = fmaxf(acc[ma][na][1] + bb1, 0.f);
            v1.x = fmaxf(acc[ma][na][2] + bb0, 0.f);
            v1.y = fmaxf(acc[ma][na][3] + bb1, 0.f);
            *(float2*)&hb[(size_t)r_ * 256 + n0 + colb] = v0;
            *(float2*)&hb[(size_t)(r_ + 8) * 256 + n0 + colb] = v1;
        }
    }
}

// ---------------------------------------------------------------------------
// Kernel 2: gates. Smem-staged Wg (odd stride), NB/16 blocks (verified R9)
// ---------------------------------------------------------------------------
template <int G>
__global__ __launch_bounds__(256) void gate_kernel(const float* __restrict__ x,
                                                   const float* __restrict__ Wg,
                                                   const float* __restrict__ bg,
                                                   int off) {
    constexpr int P = G + 1;  // odd stride
    float* wsh = (float*)dynsm;          // [1024][P]
    float* bgs = wsh + 1024 * P;         // [G]
    float* sred = bgs + G;               // [8][G]
    const int t = threadIdx.x, w = t >> 5, lane = t & 31;

    for (int i = t; i < 1024 * G; i += 256) {
        const int f = i / G;
        wsh[f * P + (i - f * G)] = Wg[i];
    }
    if (t < G) bgs[t] = bg[t];
    __syncthreads();

    const size_t brow0 = (size_t)blockIdx.x * 16 + w * 2;
    #pragma unroll
    for (int r = 0; r < 2; r++) {
        const float* xr = x + (brow0 + r) * NF;
        float acc[G];
        #pragma unroll
        for (int c = 0; c < G; c++) acc[c] = 0.f;
        for (int i = 0; i < 32; i++) {
            const float xv = xr[lane + 32 * i];
            const float* wr = wsh + (lane + 32 * i) * P;
            #pragma unroll
            for (int c = 0; c < G; c++) acc[c] += xv * wr[c];
        }
        #pragma unroll
        for (int c = 0; c < G; c++) {
            #pragma unroll
            for (int o = 16; o > 0; o >>= 1)
                acc[c] += __shfl_xor_sync(0xffffffffu, acc[c], o);
        }
        if (lane == 0) {
            #pragma unroll
            for (int c = 0; c < G; c++) sred[w * G + c] = acc[c];
        }
        __syncwarp();
        float logit = (lane < G) ? sred[w * G + lane] + bgs[lane] : -1e30f;
        float m = logit;
        #pragma unroll
        for (int o = 16; o > 0; o >>= 1)
            m = fmaxf(m, __shfl_xor_sync(0xffffffffu, m, o));
        float ex = (lane < G) ? expf(logit - m) : 0.f;
        float sum = ex;
        #pragma unroll
        for (int o = 16; o > 0; o >>= 1)
            sum += __shfl_xor_sync(0xffffffffu, sum, o);
        if (lane < G) g_gates[(brow0 + r) * 28 + off + lane] = ex / sum;
    }
}

// ---------------------------------------------------------------------------
// Kernel 3: layer-2 + relu + gated combine (unchanged, verified)
// ---------------------------------------------------------------------------
struct CArgs { const float* W2[3]; const float* b2[3]; };

#define CS_W2  0
#define CS_HS  16384
#define CS_B2  (16384 + 1024)
#define CS_GS  (16384 + 1024 + 256)
#define CS_FLOATS (16384 + 1024 + 256 + 16 * 28)
#define CS_BYTES (CS_FLOATS * 4)

__global__ __launch_bounds__(256) void combine_kernel(CArgs args, float* __restrict__ out) {
    float* cs0 = (float*)dynsm;
    float* W2s = cs0 + CS_W2;
    float* Hs  = cs0 + CS_HS;
    float* b2s = cs0 + CS_B2;
    float* gsh = cs0 + CS_GS;

    const int t = threadIdx.x;
    const int row0 = blockIdx.x * 16;

    for (int i = t; i < 16 * 28; i += 256)
        gsh[i] = g_gates[(size_t)(row0 + i / 28) * 28 + (i % 28)];

    float oA[16], oS[16], oB[16];
    #pragma unroll
    for (int r = 0; r < 16; r++) { oA[r] = 0.f; oS[r] = 0.f; oB[r] = 0.f; }

    const int hr = t >> 4;
    const int h4 = (t & 15) * 4;

    for (int e = 0; e < 12; e++) {
        const int grp = e >> 2;
        const int el  = e & 3;
        __syncthreads();
        const float4* w2g = (const float4*)(args.W2[grp] + (size_t)el * NH * ND);
        float4* w2s4 = (float4*)W2s;
        #pragma unroll
        for (int i = 0; i < 16; i++) w2s4[i * 256 + t] = w2g[i * 256 + t];
        b2s[t] = args.b2[grp][el * 256 + t];
        *(float4*)&Hs[hr * 64 + h4] =
            *(const float4*)(g_hid + (size_t)grp * NB * 256 +
                             (size_t)(row0 + hr) * 256 + el * 64 + h4);
        __syncthreads();

        unsigned long long tp[16];
        #pragma unroll
        for (int r = 0; r < 16; r++) tp[r] = 0ull;

        #pragma unroll
        for (int hp = 0; hp < 32; hp++) {
            const float w0 = W2s[(2 * hp) * 256 + t];
            const float w1 = W2s[(2 * hp + 1) * 256 + t];
            unsigned long long wpk;
            PACK2(wpk, __float_as_uint(w0), __float_as_uint(w1));
            #pragma unroll
            for (int r = 0; r < 16; r++) {
                const unsigned long long hv = *(const unsigned long long*)&Hs[r * 64 + 2 * hp];
                FMA2(tp[r], hv, wpk);
            }
        }

        #pragma unroll
        for (int r = 0; r < 16; r++) {
            unsigned int u0, u1;
            UNPACK2(u0, u1, tp[r]);
            float val = __uint_as_float(u0) + __uint_as_float(u1) + b2s[t];
            val = fmaxf(val, 0.f);
            const float* g = &gsh[r * 28];
            const float cS = g[8 + e];
            float cA = 0.f, cB = 0.f;
            if (e < 8) cA = g[e];
            if (e >= 8) cB = g[12 + e];
            else if (e >= 4) cB = g[20 + e];
            oA[r] += cA * val;
            oS[r] += cS * val;
            oB[r] += cB * val;
        }
    }

    #pragma unroll
    for (int r = 0; r < 16; r++) {
        const size_t rowoff = (size_t)(row0 + r) * 256 + t;
        out[rowoff]              = oA[r];
        out[(size_t)BD + rowoff] = oS[r];
        out[2ull * BD + rowoff]  = oB[r];
    }
}

// ---------------------------------------------------------------------------
// Launcher
// ---------------------------------------------------------------------------
extern "C" void kernel_launch(void* const* d_in, const int* in_sizes, int n_in,
                              void* d_out, int out_size) {
    (void)in_sizes; (void)n_in; (void)out_size;
    const float* x_A = (const float*)d_in[0];
    const float* x_S = (const float*)d_in[1];
    const float* x_B = (const float*)d_in[2];
    const float* W1A = (const float*)d_in[3];
    const float* b1A = (const float*)d_in[4];
    const float* W2A = (const float*)d_in[5];
    const float* b2A = (const float*)d_in[6];
    const float* W1S = (const float*)d_in[7];
    const float* b1S = (const float*)d_in[8];
    const float* W2S = (const float*)d_in[9];
    const float* b2S = (const float*)d_in[10];
    const float* W1B = (const float*)d_in[11];
    const float* b1B = (const float*)d_in[12];
    const float* W2B = (const float*)d_in[13];
    const float* b2B = (const float*)d_in[14];
    const float* WgA = (const float*)d_in[15];
    const float* bgA = (const float*)d_in[16];
    const float* WgB = (const float*)d_in[17];
    const float* bgB = (const float*)d_in[18];
    const float* WgS = (const float*)d_in[19];
    const float* bgS = (const float*)d_in[20];
    float* out = (float*)d_out;

    cudaFuncSetAttribute(gate_kernel<8>, cudaFuncAttributeMaxDynamicSharedMemorySize,
                         (1024 * 9 + 8 + 64) * 4);
    cudaFuncSetAttribute(gate_kernel<12>, cudaFuncAttributeMaxDynamicSharedMemorySize,
                         (1024 * 13 + 12 + 96) * 4);
    cudaFuncSetAttribute(combine_kernel, cudaFuncAttributeMaxDynamicSharedMemorySize, CS_BYTES);

    G1Args g1;
    g1.x[0] = x_A;  g1.x[1] = x_S;  g1.x[2] = x_B;
    g1.W1[0] = W1A; g1.W1[1] = W1S; g1.W1[2] = W1B;
    g1.b1[0] = b1A; g1.b1[1] = b1S; g1.b1[2] = b1B;
    gemm1_kernel<<<dim3(NB / 128, 2, 3), 256>>>(g1);

    gate_kernel<8><<<NB / 16, 256, (1024 * 9 + 8 + 64) * 4>>>(x_A, WgA, bgA, 0);
    gate_kernel<12><<<NB / 16, 256, (1024 * 13 + 12 + 96) * 4>>>(x_S, WgS, bgS, 8);
    gate_kernel<8><<<NB / 16, 256, (1024 * 9 + 8 + 64) * 4>>>(x_B, WgB, bgB, 20);

    CArgs c2;
    c2.W2[0] = W2A; c2.W2[1] = W2S; c2.W2[2] = W2B;
    c2.b2[0] = b2A; c2.b2[1] = b2S; c2.b2[2] = b2B;
    combine_kernel<<<NB / 16, 256, CS_BYTES>>>(c2, out);
}

// round 12
// speedup vs baseline: 1.1252x; 1.1252x over previous
#include <cuda_runtime.h>
#include <cuda_fp16.h>
#include <cstdint>

// Problem dims
#define NB   16384
#define NF   1024
#define NH   64
#define ND   256
#define BD   (NB * ND)

// ---------------------------------------------------------------------------
// Scratch (device globals — no allocations allowed)
// ---------------------------------------------------------------------------
__device__ float  g_hid[3ull * NB * 256];    // per-group hidden [B, 256], relu'd
__device__ float  g_gates[(size_t)NB * 28];  // per row: gA[8] | gS[12] | gB[8]
__device__ __half g_xh[3ull * NB * NF];      // x in fp16
__device__ __half g_w1h[3ull * 256 * NF];    // W1 transposed [grp][n=e*64+h][f], fp16

extern __shared__ char dynsm[];

// ---------------------------------------------------------------------------
// Helpers
// ---------------------------------------------------------------------------
__device__ __forceinline__ uint32_t h2pack(float a, float b) {
    __half2 h = __floats2half2_rn(a, b);
    return *(uint32_t*)&h;
}
__device__ __forceinline__ uint32_t smem_to_u32(const void* p) {
    uint32_t a;
    asm("{ .reg .u64 t; cvta.to.shared.u64 t, %1; cvt.u32.u64 %0, t; }" : "=r"(a) : "l"(p));
    return a;
}

// m16n8k16 fp16 MMA, fp32 accumulate (native HMMA, sm_80 PTX)
#define MMA_F16(c, a, b) \
    asm("mma.sync.aligned.m16n8k16.row.col.f32.f16.f16.f32 " \
        "{%0,%1,%2,%3}, {%4,%5,%6,%7}, {%8,%9}, {%0,%1,%2,%3};" \
        : "+f"((c)[0]), "+f"((c)[1]), "+f"((c)[2]), "+f"((c)[3]) \
        : "r"((a)[0]), "r"((a)[1]), "r"((a)[2]), "r"((a)[3]), \
          "r"((b)[0]), "r"((b)[1]))

#define LDSM4(rv, addr) \
    asm volatile("ldmatrix.sync.aligned.m8n8.x4.shared.b16 {%0,%1,%2,%3}, [%4];" \
        : "=r"((rv)[0]), "=r"((rv)[1]), "=r"((rv)[2]), "=r"((rv)[3]) : "r"(addr))

#define CP_ASYNC16(dst, src) \
    asm volatile("cp.async.cg.shared.global [%0], [%1], 16;" :: "r"(dst), "l"(src))
#define CP_COMMIT()  asm volatile("cp.async.commit_group;" ::: "memory")
#define CP_WAIT2()   asm volatile("cp.async.wait_group 2;" ::: "memory")

// Packed f32x2 helpers (combine kernel)
#define FMA2(acc, a, b) asm("fma.rn.f32x2 %0, %1, %2, %0;" : "+l"(acc) : "l"(a), "l"(b))
#define PACK2(dst, lo, hi) asm("mov.b64 %0, {%1, %2};" : "=l"(dst) : "r"(lo), "r"(hi))
#define UNPACK2(lo, hi, v) asm("mov.b64 {%0, %1}, %2;" : "=r"(lo), "=r"(hi) : "l"(v))

// ---------------------------------------------------------------------------
// Kernel 0a: convert x -> fp16 (one launch per group)
// ---------------------------------------------------------------------------
__global__ __launch_bounds__(256) void convx_kernel(const float* __restrict__ src, int grp) {
    __half* dst = g_xh + (size_t)grp * NB * NF;
    const size_t i = (size_t)blockIdx.x * 256 + threadIdx.x;   // 8 floats each
    const float4 f0 = ((const float4*)src)[2 * i];
    const float4 f1 = ((const float4*)src)[2 * i + 1];
    uint4 o;
    o.x = h2pack(f0.x, f0.y); o.y = h2pack(f0.z, f0.w);
    o.z = h2pack(f1.x, f1.y); o.w = h2pack(f1.z, f1.w);
    ((uint4*)dst)[i] = o;
}

// ---------------------------------------------------------------------------
// Kernel 0b: W1 [E,F,H] -> g_w1h [grp][n=e*64+h][f] fp16 (smem transpose)
// ---------------------------------------------------------------------------
struct TArgs { const float* W1[3]; };

__global__ __launch_bounds__(256) void convw_kernel(TArgs a) {
    __shared__ float sm[64][65];
    const int t = threadIdx.x;
    const int f0 = blockIdx.x * 64;
    const int e  = blockIdx.y;
    const int grp = blockIdx.z;
    const float* W1 = a.W1[grp] + (size_t)e * NF * NH + (size_t)f0 * NH;

    for (int i = t; i < 4096; i += 256) {
        const int fl = i >> 6, h = i & 63;
        sm[fl][h] = W1[(size_t)fl * 64 + h];
    }
    __syncthreads();
    uint32_t* dst = (uint32_t*)g_w1h;
    for (int i = t; i < 2048; i += 256) {
        const int nl = i >> 5, p = i & 31;
        dst[((size_t)grp * 256 + e * 64 + nl) * (NF / 2) + (f0 >> 1) + p] =
            h2pack(sm[2 * p][nl], sm[2 * p + 1][nl]);
    }
}

// ---------------------------------------------------------------------------
// Kernel 1: layer-1 GEMM. fp16 HMMA + cp.async 4-stage + ldmatrix.
// CTA tile 128x128, K-chunk 32 (32 chunks). 8 warps 4(m)x2(n), warp 32x64.
// Smem row stride 80 B (20 banks, coprime 32 -> ldmatrix conflict-free).
// Stage = A[128][80] + B[128][80] = 20480 B; 4 stages = 81920 B dynamic.
// ---------------------------------------------------------------------------
struct G1Args { const float* b1[3]; };

#define STG_BYTES 20480

__global__ __launch_bounds__(256) void gemm1_kernel(G1Args args) {
    __shared__ float bias_s[256];
    const uint32_t sb = smem_to_u32(dynsm);

    const int t = threadIdx.x, lane = t & 31, w = t >> 5;
    const int wm = w >> 1, wn = w & 1;
    const int g = lane >> 2, tt = lane & 3;
    const int row0 = blockIdx.x * 128;
    const int n0   = blockIdx.y * 128;
    const int grp  = blockIdx.z;

    bias_s[t] = args.b1[grp][t];

    // staging role: t<128 -> A row t; t>=128 -> B row t-128
    const bool isA = t < 128;
    const int rr = isA ? t : (t - 128);
    const __half* gsrc = isA
        ? (g_xh  + ((size_t)grp * NB  + row0 + rr) * NF)
        : (g_w1h + ((size_t)grp * 256 + n0   + rr) * NF);
    const uint32_t sdst = sb + (isA ? 0u : 10240u) + (uint32_t)rr * 80u;

    // ldmatrix lane address components
    const int jj = lane >> 3, r8 = lane & 7;
    const uint32_t aoff = (uint32_t)((r8 + (jj & 1) * 8) * 80 + (jj >> 1) * 16)
                          + (uint32_t)(wm * 32) * 80u;
    const uint32_t boff = (uint32_t)((r8 + (jj >> 1) * 8) * 80 + (jj & 1) * 16)
                          + (uint32_t)(wn * 64) * 80u + 10240u;

    float acc[2][8][4];
    #pragma unroll
    for (int ma = 0; ma < 2; ma++)
        #pragma unroll
        for (int na = 0; na < 8; na++)
            #pragma unroll
            for (int i = 0; i < 4; i++) acc[ma][na][i] = 0.f;

    auto issue = [&](int c) {
        const uint32_t d = sdst + (uint32_t)(c & 3) * STG_BYTES;
        const __half* s = gsrc + c * 32;
        #pragma unroll
        for (int seg = 0; seg < 4; seg++)
            CP_ASYNC16(d + seg * 16, s + seg * 8);
    };

    issue(0); CP_COMMIT();
    issue(1); CP_COMMIT();
    issue(2); CP_COMMIT();

    for (int c = 0; c < 32; c++) {
        CP_WAIT2();             // group c complete (<=2 of {c+1,c+2,...} pending)
        __syncthreads();        // all warps done with stage (c-1): safe to overwrite
        if (c + 3 < 32) issue(c + 3);
        CP_COMMIT();            // always commit (empty in tail) -> uniform counting

        const uint32_t stb = sb + (uint32_t)(c & 3) * STG_BYTES;
        #pragma unroll
        for (int kh = 0; kh < 2; kh++) {
            uint32_t a[2][4];
            #pragma unroll
            for (int ma = 0; ma < 2; ma++)
                LDSM4(a[ma], stb + aoff + ma * 16 * 80 + kh * 32);
            #pragma unroll
            for (int nt = 0; nt < 4; nt++) {
                uint32_t b[4];
                LDSM4(b, stb + boff + nt * 16 * 80 + kh * 32);
                uint32_t b01[2] = {b[0], b[1]};
                uint32_t b23[2] = {b[2], b[3]};
                MMA_F16(acc[0][nt * 2],     a[0], b01);
                MMA_F16(acc[1][nt * 2],     a[1], b01);
                MMA_F16(acc[0][nt * 2 + 1], a[0], b23);
                MMA_F16(acc[1][nt * 2 + 1], a[1], b23);
            }
        }
    }

    // epilogue: bias + relu, float2 stores (verified in R9/R10; global bias idx)
    float* hb = g_hid + (size_t)grp * NB * 256;
    #pragma unroll
    for (int ma = 0; ma < 2; ma++) {
        const int r_ = row0 + wm * 32 + ma * 16 + g;
        #pragma unroll
        for (int na = 0; na < 8; na++) {
            const int colb = wn * 64 + na * 8 + 2 * tt;
            const float bb0 = bias_s[n0 + colb];
            const float bb1 = bias_s[n0 + colb + 1];
            float2 v0, v1;
            v0.x = fmaxf(acc[ma][na][0] + bb0, 0.f);
            v0.y = fmaxf(acc[ma][na][1] + bb1, 0.f);
            v1.x = fmaxf(acc[ma][na][2] + bb0, 0.f);
            v1.y = fmaxf(acc[ma][na][3] + bb1, 0.f);
            *(float2*)&hb[(size_t)r_ * 256 + n0 + colb] = v0;
            *(float2*)&hb[(size_t)(r_ + 8) * 256 + n0 + colb] = v1;
        }
    }
}

// ---------------------------------------------------------------------------
// Kernel 2: gates. Smem-staged Wg (odd stride), NB/16 blocks (verified R9)
// ---------------------------------------------------------------------------
template <int G>
__global__ __launch_bounds__(256) void gate_kernel(const float* __restrict__ x,
                                                   const float* __restrict__ Wg,
                                                   const float* __restrict__ bg,
                                                   int off) {
    constexpr int P = G + 1;  // odd stride
    float* wsh = (float*)dynsm;          // [1024][P]
    float* bgs = wsh + 1024 * P;         // [G]
    float* sred = bgs + G;               // [8][G]
    const int t = threadIdx.x, w = t >> 5, lane = t & 31;

    for (int i = t; i < 1024 * G; i += 256) {
        const int f = i / G;
        wsh[f * P + (i - f * G)] = Wg[i];
    }
    if (t < G) bgs[t] = bg[t];
    __syncthreads();

    const size_t brow0 = (size_t)blockIdx.x * 16 + w * 2;
    #pragma unroll
    for (int r = 0; r < 2; r++) {
        const float* xr = x + (brow0 + r) * NF;
        float acc[G];
        #pragma unroll
        for (int c = 0; c < G; c++) acc[c] = 0.f;
        for (int i = 0; i < 32; i++) {
            const float xv = xr[lane + 32 * i];
            const float* wr = wsh + (lane + 32 * i) * P;
            #pragma unroll
            for (int c = 0; c < G; c++) acc[c] += xv * wr[c];
        }
        #pragma unroll
        for (int c = 0; c < G; c++) {
            #pragma unroll
            for (int o = 16; o > 0; o >>= 1)
                acc[c] += __shfl_xor_sync(0xffffffffu, acc[c], o);
        }
        if (lane == 0) {
            #pragma unroll
            for (int c = 0; c < G; c++) sred[w * G + c] = acc[c];
        }
        __syncwarp();
        float logit = (lane < G) ? sred[w * G + lane] + bgs[lane] : -1e30f;
        float m = logit;
        #pragma unroll
        for (int o = 16; o > 0; o >>= 1)
            m = fmaxf(m, __shfl_xor_sync(0xffffffffu, m, o));
        float ex = (lane < G) ? expf(logit - m) : 0.f;
        float sum = ex;
        #pragma unroll
        for (int o = 16; o > 0; o >>= 1)
            sum += __shfl_xor_sync(0xffffffffu, sum, o);
        if (lane < G) g_gates[(brow0 + r) * 28 + off + lane] = ex / sum;
    }
}

// ---------------------------------------------------------------------------
// Kernel 3: layer-2 + relu + gated combine (unchanged, verified)
// ---------------------------------------------------------------------------
struct CArgs { const float* W2[3]; const float* b2[3]; };

#define CS_W2  0
#define CS_HS  16384
#define CS_B2  (16384 + 1024)
#define CS_GS  (16384 + 1024 + 256)
#define CS_FLOATS (16384 + 1024 + 256 + 16 * 28)
#define CS_BYTES (CS_FLOATS * 4)

__global__ __launch_bounds__(256) void combine_kernel(CArgs args, float* __restrict__ out) {
    float* cs0 = (float*)dynsm;
    float* W2s = cs0 + CS_W2;
    float* Hs  = cs0 + CS_HS;
    float* b2s = cs0 + CS_B2;
    float* gsh = cs0 + CS_GS;

    const int t = threadIdx.x;
    const int row0 = blockIdx.x * 16;

    for (int i = t; i < 16 * 28; i += 256)
        gsh[i] = g_gates[(size_t)(row0 + i / 28) * 28 + (i % 28)];

    float oA[16], oS[16], oB[16];
    #pragma unroll
    for (int r = 0; r < 16; r++) { oA[r] = 0.f; oS[r] = 0.f; oB[r] = 0.f; }

    const int hr = t >> 4;
    const int h4 = (t & 15) * 4;

    for (int e = 0; e < 12; e++) {
        const int grp = e >> 2;
        const int el  = e & 3;
        __syncthreads();
        const float4* w2g = (const float4*)(args.W2[grp] + (size_t)el * NH * ND);
        float4* w2s4 = (float4*)W2s;
        #pragma unroll
        for (int i = 0; i < 16; i++) w2s4[i * 256 + t] = w2g[i * 256 + t];
        b2s[t] = args.b2[grp][el * 256 + t];
        *(float4*)&Hs[hr * 64 + h4] =
            *(const float4*)(g_hid + (size_t)grp * NB * 256 +
                             (size_t)(row0 + hr) * 256 + el * 64 + h4);
        __syncthreads();

        unsigned long long tp[16];
        #pragma unroll
        for (int r = 0; r < 16; r++) tp[r] = 0ull;

        #pragma unroll
        for (int hp = 0; hp < 32; hp++) {
            const float w0 = W2s[(2 * hp) * 256 + t];
            const float w1 = W2s[(2 * hp + 1) * 256 + t];
            unsigned long long wpk;
            PACK2(wpk, __float_as_uint(w0), __float_as_uint(w1));
            #pragma unroll
            for (int r = 0; r < 16; r++) {
                const unsigned long long hv = *(const unsigned long long*)&Hs[r * 64 + 2 * hp];
                FMA2(tp[r], hv, wpk);
            }
        }

        #pragma unroll
        for (int r = 0; r < 16; r++) {
            unsigned int u0, u1;
            UNPACK2(u0, u1, tp[r]);
            float val = __uint_as_float(u0) + __uint_as_float(u1) + b2s[t];
            val = fmaxf(val, 0.f);
            const float* g = &gsh[r * 28];
            const float cS = g[8 + e];
            float cA = 0.f, cB = 0.f;
            if (e < 8) cA = g[e];
            if (e >= 8) cB = g[12 + e];
            else if (e >= 4) cB = g[20 + e];
            oA[r] += cA * val;
            oS[r] += cS * val;
            oB[r] += cB * val;
        }
    }

    #pragma unroll
    for (int r = 0; r < 16; r++) {
        const size_t rowoff = (size_t)(row0 + r) * 256 + t;
        out[rowoff]              = oA[r];
        out[(size_t)BD + rowoff] = oS[r];
        out[2ull * BD + rowoff]  = oB[r];
    }
}

// ---------------------------------------------------------------------------
// Launcher
// ---------------------------------------------------------------------------
extern "C" void kernel_launch(void* const* d_in, const int* in_sizes, int n_in,
                              void* d_out, int out_size) {
    (void)in_sizes; (void)n_in; (void)out_size;
    const float* x_A = (const float*)d_in[0];
    const float* x_S = (const float*)d_in[1];
    const float* x_B = (const float*)d_in[2];
    const float* W1A = (const float*)d_in[3];
    const float* b1A = (const float*)d_in[4];
    const float* W2A = (const float*)d_in[5];
    const float* b2A = (const float*)d_in[6];
    const float* W1S = (const float*)d_in[7];
    const float* b1S = (const float*)d_in[8];
    const float* W2S = (const float*)d_in[9];
    const float* b2S = (const float*)d_in[10];
    const float* W1B = (const float*)d_in[11];
    const float* b1B = (const float*)d_in[12];
    const float* W2B = (const float*)d_in[13];
    const float* b2B = (const float*)d_in[14];
    const float* WgA = (const float*)d_in[15];
    const float* bgA = (const float*)d_in[16];
    const float* WgB = (const float*)d_in[17];
    const float* bgB = (const float*)d_in[18];
    const float* WgS = (const float*)d_in[19];
    const float* bgS = (const float*)d_in[20];
    float* out = (float*)d_out;

    cudaFuncSetAttribute(gemm1_kernel, cudaFuncAttributeMaxDynamicSharedMemorySize,
                         4 * STG_BYTES);
    cudaFuncSetAttribute(gate_kernel<8>, cudaFuncAttributeMaxDynamicSharedMemorySize,
                         (1024 * 9 + 8 + 64) * 4);
    cudaFuncSetAttribute(gate_kernel<12>, cudaFuncAttributeMaxDynamicSharedMemorySize,
                         (1024 * 13 + 12 + 96) * 4);
    cudaFuncSetAttribute(combine_kernel, cudaFuncAttributeMaxDynamicSharedMemorySize, CS_BYTES);

    // converts: x (3 groups) and W1 transpose
    convx_kernel<<<NB * NF / 8 / 256, 256>>>(x_A, 0);
    convx_kernel<<<NB * NF / 8 / 256, 256>>>(x_S, 1);
    convx_kernel<<<NB * NF / 8 / 256, 256>>>(x_B, 2);
    TArgs ta;
    ta.W1[0] = W1A; ta.W1[1] = W1S; ta.W1[2] = W1B;
    convw_kernel<<<dim3(16, 4, 3), 256>>>(ta);

    G1Args g1;
    g1.b1[0] = b1A; g1.b1[1] = b1S; g1.b1[2] = b1B;
    gemm1_kernel<<<dim3(NB / 128, 2, 3), 256, 4 * STG_BYTES>>>(g1);

    gate_kernel<8><<<NB / 16, 256, (1024 * 9 + 8 + 64) * 4>>>(x_A, WgA, bgA, 0);
    gate_kernel<12><<<NB / 16, 256, (1024 * 13 + 12 + 96) * 4>>>(x_S, WgS, bgS, 8);
    gate_kernel<8><<<NB / 16, 256, (1024 * 9 + 8 + 64) * 4>>>(x_B, WgB, bgB, 20);

    CArgs c2;
    c2.W2[0] = W2A; c2.W2[1] = W2S; c2.W2[2] = W2B;
    c2.b2[0] = b2A; c2.b2[1] = b2S; c2.b2[2] = b2B;
    combine_kernel<<<NB / 16, 256, CS_BYTES>>>(c2, out);
}

// round 13
// speedup vs baseline: 1.6365x; 1.4544x over previous
#include <cuda_runtime.h>
#include <cuda_fp16.h>
#include <cstdint>

// Problem dims
#define NB   16384
#define NF   1024
#define NH   64
#define ND   256
#define BD   (NB * ND)

// ---------------------------------------------------------------------------
// Scratch (device globals — no allocations allowed)
// ---------------------------------------------------------------------------
__device__ float  g_gates[(size_t)NB * 28];  // per row: gA[8] | gS[12] | gB[8]
__device__ __half g_xh[3ull * NB * NF];      // x in fp16
__device__ __half g_w1h[3ull * 256 * NF];    // W1 transposed [grp][n=e*64+h][f], fp16
__device__ __half g_hidh[3ull * NB * 256];   // hidden [grp][b][256] fp16, relu'd
__device__ __half g_w2h[12ull * 256 * 64];   // W2 transposed [e][n=d][k=h], fp16

extern __shared__ char dynsm[];

// ---------------------------------------------------------------------------
// Helpers
// ---------------------------------------------------------------------------
__device__ __forceinline__ uint32_t h2pack(float a, float b) {
    __half2 h = __floats2half2_rn(a, b);
    return *(uint32_t*)&h;
}
__device__ __forceinline__ uint32_t smem_to_u32(const void* p) {
    uint32_t a;
    asm("{ .reg .u64 t; cvta.to.shared.u64 t, %1; cvt.u32.u64 %0, t; }" : "=r"(a) : "l"(p));
    return a;
}

// m16n8k16 fp16 MMA, fp32 accumulate (native HMMA, sm_80 PTX)
#define MMA_F16(c, a, b) \
    asm("mma.sync.aligned.m16n8k16.row.col.f32.f16.f16.f32 " \
        "{%0,%1,%2,%3}, {%4,%5,%6,%7}, {%8,%9}, {%0,%1,%2,%3};" \
        : "+f"((c)[0]), "+f"((c)[1]), "+f"((c)[2]), "+f"((c)[3]) \
        : "r"((a)[0]), "r"((a)[1]), "r"((a)[2]), "r"((a)[3]), \
          "r"((b)[0]), "r"((b)[1]))

#define LDSM4(rv, addr) \
    asm volatile("ldmatrix.sync.aligned.m8n8.x4.shared.b16 {%0,%1,%2,%3}, [%4];" \
        : "=r"((rv)[0]), "=r"((rv)[1]), "=r"((rv)[2]), "=r"((rv)[3]) : "r"(addr))

#define CP_ASYNC16(dst, src) \
    asm volatile("cp.async.cg.shared.global [%0], [%1], 16;" :: "r"(dst), "l"(src))
#define CP_COMMIT()  asm volatile("cp.async.commit_group;" ::: "memory")
#define CP_WAIT3()   asm volatile("cp.async.wait_group 3;" ::: "memory")
#define CP_WAIT1()   asm volatile("cp.async.wait_group 1;" ::: "memory")

// ---------------------------------------------------------------------------
// Kernel 0a: convert x -> fp16 (one launch per group)
// ---------------------------------------------------------------------------
__global__ __launch_bounds__(256) void convx_kernel(const float* __restrict__ src, int grp) {
    __half* dst = g_xh + (size_t)grp * NB * NF;
    const size_t i = (size_t)blockIdx.x * 256 + threadIdx.x;   // 8 floats each
    const float4 f0 = ((const float4*)src)[2 * i];
    const float4 f1 = ((const float4*)src)[2 * i + 1];
    uint4 o;
    o.x = h2pack(f0.x, f0.y); o.y = h2pack(f0.z, f0.w);
    o.z = h2pack(f1.x, f1.y); o.w = h2pack(f1.z, f1.w);
    ((uint4*)dst)[i] = o;
}

// ---------------------------------------------------------------------------
// Kernel 0b: W1 [E,F,H] -> g_w1h [grp][n=e*64+h][f] fp16 (smem transpose)
// ---------------------------------------------------------------------------
struct TArgs { const float* W1[3]; };

__global__ __launch_bounds__(256) void convw_kernel(TArgs a) {
    __shared__ float sm[64][65];
    const int t = threadIdx.x;
    const int f0 = blockIdx.x * 64;
    const int e  = blockIdx.y;
    const int grp = blockIdx.z;
    const float* W1 = a.W1[grp] + (size_t)e * NF * NH + (size_t)f0 * NH;

    for (int i = t; i < 4096; i += 256) {
        const int fl = i >> 6, h = i & 63;
        sm[fl][h] = W1[(size_t)fl * 64 + h];
    }
    __syncthreads();
    uint32_t* dst = (uint32_t*)g_w1h;
    for (int i = t; i < 2048; i += 256) {
        const int nl = i >> 5, p = i & 31;
        dst[((size_t)grp * 256 + e * 64 + nl) * (NF / 2) + (f0 >> 1) + p] =
            h2pack(sm[2 * p][nl], sm[2 * p + 1][nl]);
    }
}

// ---------------------------------------------------------------------------
// Kernel 0c: W2 [E,H=64,D=256] -> g_w2h [e][n=d][k=h] fp16 (smem transpose)
// grid (nTile=4, el=4, grp=3); tile [64 k][64 n]
// ---------------------------------------------------------------------------
struct T2Args { const float* W2[3]; };

__global__ __launch_bounds__(256) void convw2_kernel(T2Args a) {
    __shared__ float sm[64][65];
    const int t = threadIdx.x;
    const int n0t = blockIdx.x * 64;
    const int el  = blockIdx.y;
    const int grp = blockIdx.z;
    const float* W2 = a.W2[grp] + (size_t)el * NH * ND;

    for (int i = t; i < 4096; i += 256) {
        const int k = i >> 6, nl = i & 63;
        sm[k][nl] = W2[(size_t)k * ND + n0t + nl];
    }
    __syncthreads();
    uint32_t* dst = (uint32_t*)g_w2h;
    for (int i = t; i < 2048; i += 256) {
        const int nl = i >> 5, p = i & 31;   // p: k-pair 0..31
        dst[((size_t)(grp * 4 + el) * 256 + n0t + nl) * 32 + p] =
            h2pack(sm[2 * p][nl], sm[2 * p + 1][nl]);
    }
}

// ---------------------------------------------------------------------------
// Kernel 1: layer-1 GEMM. fp16 HMMA + cp.async 5-stage + ldmatrix.
// CTA tile 128x128, K-chunk 32 (32 chunks). 8 warps 4(m)x2(n), warp 32x64.
// Smem row stride 80 B (20 banks, coprime 32 -> ldmatrix conflict-free).
// Stage = A[128][80] + B[128][80] = 20480 B; 5 stages = 102400 B dynamic.
// ---------------------------------------------------------------------------
struct G1Args { const float* b1[3]; };

#define STG_BYTES 20480
#define G1_SMEM   (5 * STG_BYTES)

__global__ __launch_bounds__(256) void gemm1_kernel(G1Args args) {
    __shared__ float bias_s[256];
    const uint32_t sb = smem_to_u32(dynsm);

    const int t = threadIdx.x, lane = t & 31, w = t >> 5;
    const int wm = w >> 1, wn = w & 1;
    const int g = lane >> 2, tt = lane & 3;
    const int row0 = blockIdx.x * 128;
    const int n0   = blockIdx.y * 128;
    const int grp  = blockIdx.z;

    bias_s[t] = args.b1[grp][t];

    // staging role: t<128 -> A row t; t>=128 -> B row t-128
    const bool isA = t < 128;
    const int rr = isA ? t : (t - 128);
    const __half* gsrc = isA
        ? (g_xh  + ((size_t)grp * NB  + row0 + rr) * NF)
        : (g_w1h + ((size_t)grp * 256 + n0   + rr) * NF);
    const uint32_t sdst = sb + (isA ? 0u : 10240u) + (uint32_t)rr * 80u;

    // ldmatrix lane address components
    const int jj = lane >> 3, r8 = lane & 7;
    const uint32_t aoff = (uint32_t)((r8 + (jj & 1) * 8) * 80 + (jj >> 1) * 16)
                          + (uint32_t)(wm * 32) * 80u;
    const uint32_t boff = (uint32_t)((r8 + (jj >> 1) * 8) * 80 + (jj & 1) * 16)
                          + (uint32_t)(wn * 64) * 80u + 10240u;

    float acc[2][8][4];
    #pragma unroll
    for (int ma = 0; ma < 2; ma++)
        #pragma unroll
        for (int na = 0; na < 8; na++)
            #pragma unroll
            for (int i = 0; i < 4; i++) acc[ma][na][i] = 0.f;

    auto issue = [&](int c, int stg) {
        const uint32_t d = sdst + (uint32_t)stg * STG_BYTES;
        const __half* s = gsrc + c * 32;
        #pragma unroll
        for (int seg = 0; seg < 4; seg++)
            CP_ASYNC16(d + seg * 16, s + seg * 8);
    };

    issue(0, 0); CP_COMMIT();
    issue(1, 1); CP_COMMIT();
    issue(2, 2); CP_COMMIT();
    issue(3, 3); CP_COMMIT();

    int scur = 0, snew = 4;   // stage indices mod 5
    for (int c = 0; c < 32; c++) {
        CP_WAIT3();             // group c complete (<=3 newer pending)
        __syncthreads();        // stage snew (== last read at c-1) free to overwrite
        if (c + 4 < 32) issue(c + 4, snew);
        CP_COMMIT();            // uniform group counting (empty in tail)

        const uint32_t stb = sb + (uint32_t)scur * STG_BYTES;
        #pragma unroll
        for (int kh = 0; kh < 2; kh++) {
            uint32_t a[2][4];
            #pragma unroll
            for (int ma = 0; ma < 2; ma++)
                LDSM4(a[ma], stb + aoff + ma * 16 * 80 + kh * 32);
            #pragma unroll
            for (int nt = 0; nt < 4; nt++) {
                uint32_t b[4];
                LDSM4(b, stb + boff + nt * 16 * 80 + kh * 32);
                uint32_t b01[2] = {b[0], b[1]};
                uint32_t b23[2] = {b[2], b[3]};
                MMA_F16(acc[0][nt * 2],     a[0], b01);
                MMA_F16(acc[1][nt * 2],     a[1], b01);
                MMA_F16(acc[0][nt * 2 + 1], a[0], b23);
                MMA_F16(acc[1][nt * 2 + 1], a[1], b23);
            }
        }
        snew = scur;                    // stage just consumed becomes reusable next iter
        scur = (scur == 4) ? 0 : scur + 1;
    }

    // epilogue: bias + relu, fp16 half2 stores (bias indexed by GLOBAL column)
    uint32_t* hb = (uint32_t*)(g_hidh + (size_t)grp * NB * 256);
    #pragma unroll
    for (int ma = 0; ma < 2; ma++) {
        const int r_ = row0 + wm * 32 + ma * 16 + g;
        #pragma unroll
        for (int na = 0; na < 8; na++) {
            const int colb = wn * 64 + na * 8 + 2 * tt;
            const float bb0 = bias_s[n0 + colb];
            const float bb1 = bias_s[n0 + colb + 1];
            hb[(size_t)r_ * 128 + (n0 + colb) / 2] =
                h2pack(fmaxf(acc[ma][na][0] + bb0, 0.f),
                       fmaxf(acc[ma][na][1] + bb1, 0.f));
            hb[(size_t)(r_ + 8) * 128 + (n0 + colb) / 2] =
                h2pack(fmaxf(acc[ma][na][2] + bb0, 0.f),
                       fmaxf(acc[ma][na][3] + bb1, 0.f));
        }
    }
}

// ---------------------------------------------------------------------------
// Kernel 2: gates. Smem-staged Wg (odd stride), NB/16 blocks (verified R9)
// ---------------------------------------------------------------------------
template <int G>
__global__ __launch_bounds__(256) void gate_kernel(const float* __restrict__ x,
                                                   const float* __restrict__ Wg,
                                                   const float* __restrict__ bg,
                                                   int off) {
    constexpr int P = G + 1;  // odd stride
    float* wsh = (float*)dynsm;          // [1024][P]
    float* bgs = wsh + 1024 * P;         // [G]
    float* sred = bgs + G;               // [8][G]
    const int t = threadIdx.x, w = t >> 5, lane = t & 31;

    for (int i = t; i < 1024 * G; i += 256) {
        const int f = i / G;
        wsh[f * P + (i - f * G)] = Wg[i];
    }
    if (t < G) bgs[t] = bg[t];
    __syncthreads();

    const size_t brow0 = (size_t)blockIdx.x * 16 + w * 2;
    #pragma unroll
    for (int r = 0; r < 2; r++) {
        const float* xr = x + (brow0 + r) * NF;
        float acc[G];
        #pragma unroll
        for (int c = 0; c < G; c++) acc[c] = 0.f;
        for (int i = 0; i < 32; i++) {
            const float xv = xr[lane + 32 * i];
            const float* wr = wsh + (lane + 32 * i) * P;
            #pragma unroll
            for (int c = 0; c < G; c++) acc[c] += xv * wr[c];
        }
        #pragma unroll
        for (int c = 0; c < G; c++) {
            #pragma unroll
            for (int o = 16; o > 0; o >>= 1)
                acc[c] += __shfl_xor_sync(0xffffffffu, acc[c], o);
        }
        if (lane == 0) {
            #pragma unroll
            for (int c = 0; c < G; c++) sred[w * G + c] = acc[c];
        }
        __syncwarp();
        float logit = (lane < G) ? sred[w * G + lane] + bgs[lane] : -1e30f;
        float m = logit;
        #pragma unroll
        for (int o = 16; o > 0; o >>= 1)
            m = fmaxf(m, __shfl_xor_sync(0xffffffffu, m, o));
        float ex = (lane < G) ? expf(logit - m) : 0.f;
        float sum = ex;
        #pragma unroll
        for (int o = 16; o > 0; o >>= 1)
            sum += __shfl_xor_sync(0xffffffffu, sum, o);
        if (lane < G) g_gates[(brow0 + r) * 28 + off + lane] = ex / sum;
    }
}

// ---------------------------------------------------------------------------
// Kernel 3: layer-2 + relu + gated combine via fp16 HMMA.
// 16 rows/CTA (M=16), 8 warps x 32 n-cols. W2 double-buffered cp.async.
// Smem: Ws[2][256][72h] | Hs[3][16][264h] | b2s[12][256]f | gsh[16][28]f
// ---------------------------------------------------------------------------
struct CArgs { const float* b2[3]; };

#define CB_WS0 0
#define CB_WS1 36864
#define CB_HS  73728
#define CB_B2  99072
#define CB_GS  111360
#define CB_SMEM 113152

__global__ __launch_bounds__(256) void combine_kernel(CArgs args, float* __restrict__ out) {
    const uint32_t sb = smem_to_u32(dynsm);
    float* b2s = (float*)(dynsm + CB_B2);   // [12][256]
    float* gsh = (float*)(dynsm + CB_GS);   // [16][28]

    const int t = threadIdx.x, lane = t & 31, w = t >> 5;
    const int g = lane >> 2, tt = lane & 3;
    const int jj = lane >> 3, r8 = lane & 7;
    const int row0 = blockIdx.x * 16;

    // stage Hs: 48 rows (3 grp x 16), 512B each; threads 0..191, quarter each
    if (t < 192) {
        const int rowi = t >> 2, q = t & 3;       // rowi = grp*16 + r
        const int grp = rowi >> 4, r = rowi & 15;
        const uint32_t d = sb + CB_HS + (uint32_t)rowi * 528u + (uint32_t)q * 128u;
        const __half* s = g_hidh + ((size_t)grp * NB + row0 + r) * 256 + q * 64;
        #pragma unroll
        for (int sg = 0; sg < 8; sg++) CP_ASYNC16(d + sg * 16, s + sg * 8);
    }
    // stage W2[0] (expert 0)
    {
        const uint32_t d = sb + CB_WS0 + (uint32_t)t * 144u;
        const __half* s = g_w2h + (size_t)t * 64;
        #pragma unroll
        for (int sg = 0; sg < 8; sg++) CP_ASYNC16(d + sg * 16, s + sg * 8);
    }
    CP_COMMIT();   // group 0: Hs + W2[0]
    // stage W2[1]
    {
        const uint32_t d = sb + CB_WS1 + (uint32_t)t * 144u;
        const __half* s = g_w2h + ((size_t)256 + t) * 64;
        #pragma unroll
        for (int sg = 0; sg < 8; sg++) CP_ASYNC16(d + sg * 16, s + sg * 8);
    }
    CP_COMMIT();   // group 1: W2[1]

    // plain loads while cp.async flies
    for (int i = t; i < 12 * 256; i += 256) {
        const int e = i >> 8, col = i & 255;
        b2s[i] = args.b2[e >> 2][(e & 3) * 256 + col];
    }
    for (int i = t; i < 16 * 28; i += 256)
        gsh[i] = g_gates[(size_t)(row0 + i / 28) * 28 + (i % 28)];

    CP_WAIT1();        // group 0 (Hs + W2[0]) complete
    __syncthreads();

    float oA[2][8], oS[2][8], oB[2][8];
    #pragma unroll
    for (int r = 0; r < 2; r++)
        #pragma unroll
        for (int i = 0; i < 8; i++) { oA[r][i] = 0.f; oS[r][i] = 0.f; oB[r][i] = 0.f; }

    for (int e = 0; e < 12; e++) {
        const uint32_t wsb = sb + ((e & 1) ? CB_WS1 : CB_WS0);
        const uint32_t hsb = sb + CB_HS + (uint32_t)(e >> 2) * 16u * 528u
                             + (uint32_t)(e & 3) * 128u;

        // A fragments (M=16, K=64): one LDSM4 per k-step
        uint32_t a[4][4];
        #pragma unroll
        for (int kk = 0; kk < 4; kk++)
            LDSM4(a[kk], hsb + (uint32_t)((r8 + (jj & 1) * 8) * 528 + (jj >> 1) * 16 + kk * 32));

        float acc[4][4];
        #pragma unroll
        for (int na = 0; na < 4; na++)
            #pragma unroll
            for (int i = 0; i < 4; i++) acc[na][i] = 0.f;

        #pragma unroll
        for (int kk = 0; kk < 4; kk++) {
            #pragma unroll
            for (int nt = 0; nt < 2; nt++) {
                uint32_t b[4];
                LDSM4(b, wsb + (uint32_t)((w * 32 + nt * 16 + r8 + (jj >> 1) * 8) * 144
                                          + (jj & 1) * 16 + kk * 32));
                uint32_t b01[2] = {b[0], b[1]};
                uint32_t b23[2] = {b[2], b[3]};
                MMA_F16(acc[nt * 2],     a[kk], b01);
                MMA_F16(acc[nt * 2 + 1], a[kk], b23);
            }
        }

        // epilogue for expert e: bias + relu + gated accumulate (verified logic)
        const float* g0 = &gsh[g * 28];
        const float* g1 = &gsh[(g + 8) * 28];
        const float cS0 = g0[8 + e], cS1 = g1[8 + e];
        float cA0 = 0.f, cA1 = 0.f, cB0 = 0.f, cB1 = 0.f;
        if (e < 8)       { cA0 = g0[e];      cA1 = g1[e]; }
        if (e >= 8)      { cB0 = g0[12 + e]; cB1 = g1[12 + e]; }
        else if (e >= 4) { cB0 = g0[20 + e]; cB1 = g1[20 + e]; }
        #pragma unroll
        for (int na = 0; na < 4; na++) {
            const int col = w * 32 + na * 8 + 2 * tt;
            const float bb0 = b2s[e * 256 + col], bb1 = b2s[e * 256 + col + 1];
            const float v00 = fmaxf(acc[na][0] + bb0, 0.f);
            const float v01 = fmaxf(acc[na][1] + bb1, 0.f);
            const float v10 = fmaxf(acc[na][2] + bb0, 0.f);
            const float v11 = fmaxf(acc[na][3] + bb1, 0.f);
            oA[0][na * 2] += cA0 * v00; oA[0][na * 2 + 1] += cA0 * v01;
            oA[1][na * 2] += cA1 * v10; oA[1][na * 2 + 1] += cA1 * v11;
            oS[0][na * 2] += cS0 * v00; oS[0][na * 2 + 1] += cS0 * v01;
            oS[1][na * 2] += cS1 * v10; oS[1][na * 2 + 1] += cS1 * v11;
            oB[0][na * 2] += cB0 * v00; oB[0][na * 2 + 1] += cB0 * v01;
            oB[1][na * 2] += cB1 * v10; oB[1][na * 2 + 1] += cB1 * v11;
        }

        // advance W2 pipeline
        __syncthreads();                       // all warps done reading Ws[e&1]
        if (e + 2 < 12) {
            const uint32_t d = sb + ((e & 1) ? CB_WS1 : CB_WS0) + (uint32_t)t * 144u;
            const __half* s = g_w2h + ((size_t)(e + 2) * 256 + t) * 64;
            #pragma unroll
            for (int sg = 0; sg < 8; sg++) CP_ASYNC16(d + sg * 16, s + sg * 8);
        }
        CP_COMMIT();
        CP_WAIT1();                            // W2[e+1] complete
        __syncthreads();
    }

    // final stores: 3 outputs x 2 rows x 4 col-pairs per thread
    #pragma unroll
    for (int r = 0; r < 2; r++) {
        const size_t rowb = (size_t)(row0 + r * 8 + g) * 256;
        #pragma unroll
        for (int na = 0; na < 4; na++) {
            const int col = w * 32 + na * 8 + 2 * tt;
            float2 vA = {oA[r][na * 2], oA[r][na * 2 + 1]};
            float2 vS = {oS[r][na * 2], oS[r][na * 2 + 1]};
            float2 vB = {oB[r][na * 2], oB[r][na * 2 + 1]};
            *(float2*)&out[rowb + col]              = vA;
            *(float2*)&out[(size_t)BD + rowb + col] = vS;
            *(float2*)&out[2ull * BD + rowb + col]  = vB;
        }
    }
}

// ---------------------------------------------------------------------------
// Launcher
// ---------------------------------------------------------------------------
extern "C" void kernel_launch(void* const* d_in, const int* in_sizes, int n_in,
                              void* d_out, int out_size) {
    (void)in_sizes; (void)n_in; (void)out_size;
    const float* x_A = (const float*)d_in[0];
    const float* x_S = (const float*)d_in[1];
    const float* x_B = (const float*)d_in[2];
    const float* W1A = (const float*)d_in[3];
    const float* b1A = (const float*)d_in[4];
    const float* W2A = (const float*)d_in[5];
    const float* b2A = (const float*)d_in[6];
    const float* W1S = (const float*)d_in[7];
    const float* b1S = (const float*)d_in[8];
    const float* W2S = (const float*)d_in[9];
    const float* b2S = (const float*)d_in[10];
    const float* W1B = (const float*)d_in[11];
    const float* b1B = (const float*)d_in[12];
    const float* W2B = (const float*)d_in[13];
    const float* b2B = (const float*)d_in[14];
    const float* WgA = (const float*)d_in[15];
    const float* bgA = (const float*)d_in[16];
    const float* WgB = (const float*)d_in[17];
    const float* bgB = (const float*)d_in[18];
    const float* WgS = (const float*)d_in[19];
    const float* bgS = (const float*)d_in[20];
    float* out = (float*)d_out;

    cudaFuncSetAttribute(gemm1_kernel, cudaFuncAttributeMaxDynamicSharedMemorySize, G1_SMEM);
    cudaFuncSetAttribute(gate_kernel<8>, cudaFuncAttributeMaxDynamicSharedMemorySize,
                         (1024 * 9 + 8 + 64) * 4);
    cudaFuncSetAttribute(gate_kernel<12>, cudaFuncAttributeMaxDynamicSharedMemorySize,
                         (1024 * 13 + 12 + 96) * 4);
    cudaFuncSetAttribute(combine_kernel, cudaFuncAttributeMaxDynamicSharedMemorySize, CB_SMEM);

    convx_kernel<<<NB * NF / 8 / 256, 256>>>(x_A, 0);
    convx_kernel<<<NB * NF / 8 / 256, 256>>>(x_S, 1);
    convx_kernel<<<NB * NF / 8 / 256, 256>>>(x_B, 2);
    TArgs ta;
    ta.W1[0] = W1A; ta.W1[1] = W1S; ta.W1[2] = W1B;
    convw_kernel<<<dim3(16, 4, 3), 256>>>(ta);
    T2Args t2;
    t2.W2[0] = W2A; t2.W2[1] = W2S; t2.W2[2] = W2B;
    convw2_kernel<<<dim3(4, 4, 3), 256>>>(t2);

    G1Args g1;
    g1.b1[0] = b1A; g1.b1[1] = b1S; g1.b1[2] = b1B;
    gemm1_kernel<<<dim3(NB / 128, 2, 3), 256, G1_SMEM>>>(g1);

    gate_kernel<8><<<NB / 16, 256, (1024 * 9 + 8 + 64) * 4>>>(x_A, WgA, bgA, 0);
    gate_kernel<12><<<NB / 16, 256, (1024 * 13 + 12 + 96) * 4>>>(x_S, WgS, bgS, 8);
    gate_kernel<8><<<NB / 16, 256, (1024 * 9 + 8 + 64) * 4>>>(x_B, WgB, bgB, 20);

    CArgs c2;
    c2.b2[0] = b2A; c2.b2[1] = b2S; c2.b2[2] = b2B;
    combine_kernel<<<NB / 16, 256, CB_SMEM>>>(c2, out);
}

// round 14
// speedup vs baseline: 1.7946x; 1.0966x over previous
#include <cuda_runtime.h>
#include <cuda_fp16.h>
#include <cstdint>

// Problem dims
#define NB   16384
#define NF   1024
#define NH   64
#define ND   256
#define BD   (NB * ND)

// ---------------------------------------------------------------------------
// Scratch (device globals — no allocations allowed)
// ---------------------------------------------------------------------------
__device__ float  g_gates[(size_t)NB * 28];  // per row: gA[8] | gS[12] | gB[8]
__device__ __half g_xh[3ull * NB * NF];      // x in fp16
__device__ __half g_w1h[3ull * 256 * NF];    // W1 transposed [grp][n=e*64+h][f], fp16
__device__ __half g_hidh[3ull * NB * 256];   // hidden [grp][b][256] fp16, relu'd
__device__ __half g_w2h[12ull * 256 * 64];   // W2 transposed [e][n=d][k=h], fp16
__device__ __half g_wgh[3ull * 32 * NF];     // Wg transposed+padded [grp][n=32][f], fp16

extern __shared__ char dynsm[];

// ---------------------------------------------------------------------------
// Helpers
// ---------------------------------------------------------------------------
__device__ __forceinline__ uint32_t h2pack(float a, float b) {
    __half2 h = __floats2half2_rn(a, b);
    return *(uint32_t*)&h;
}
__device__ __forceinline__ uint32_t smem_to_u32(const void* p) {
    uint32_t a;
    asm("{ .reg .u64 t; cvta.to.shared.u64 t, %1; cvt.u32.u64 %0, t; }" : "=r"(a) : "l"(p));
    return a;
}

// m16n8k16 fp16 MMA, fp32 accumulate (native HMMA, sm_80 PTX)
#define MMA_F16(c, a, b) \
    asm("mma.sync.aligned.m16n8k16.row.col.f32.f16.f16.f32 " \
        "{%0,%1,%2,%3}, {%4,%5,%6,%7}, {%8,%9}, {%0,%1,%2,%3};" \
        : "+f"((c)[0]), "+f"((c)[1]), "+f"((c)[2]), "+f"((c)[3]) \
        : "r"((a)[0]), "r"((a)[1]), "r"((a)[2]), "r"((a)[3]), \
          "r"((b)[0]), "r"((b)[1]))

#define LDSM4(rv, addr) \
    asm volatile("ldmatrix.sync.aligned.m8n8.x4.shared.b16 {%0,%1,%2,%3}, [%4];" \
        : "=r"((rv)[0]), "=r"((rv)[1]), "=r"((rv)[2]), "=r"((rv)[3]) : "r"(addr))

#define CP_ASYNC16(dst, src) \
    asm volatile("cp.async.cg.shared.global [%0], [%1], 16;" :: "r"(dst), "l"(src))
#define CP_COMMIT()  asm volatile("cp.async.commit_group;" ::: "memory")
#define CP_WAIT2()   asm volatile("cp.async.wait_group 2;" ::: "memory")
#define CP_WAIT1()   asm volatile("cp.async.wait_group 1;" ::: "memory")

// ---------------------------------------------------------------------------
// Kernel 0a: convert x -> fp16 (one launch per group)
// ---------------------------------------------------------------------------
__global__ __launch_bounds__(256) void convx_kernel(const float* __restrict__ src, int grp) {
    __half* dst = g_xh + (size_t)grp * NB * NF;
    const size_t i = (size_t)blockIdx.x * 256 + threadIdx.x;   // 8 floats each
    const float4 f0 = ((const float4*)src)[2 * i];
    const float4 f1 = ((const float4*)src)[2 * i + 1];
    uint4 o;
    o.x = h2pack(f0.x, f0.y); o.y = h2pack(f0.z, f0.w);
    o.z = h2pack(f1.x, f1.y); o.w = h2pack(f1.z, f1.w);
    ((uint4*)dst)[i] = o;
}

// ---------------------------------------------------------------------------
// Kernel 0b: W1 [E,F,H] -> g_w1h [grp][n=e*64+h][f] fp16 (smem transpose)
// ---------------------------------------------------------------------------
struct TArgs { const float* W1[3]; };

__global__ __launch_bounds__(256) void convw_kernel(TArgs a) {
    __shared__ float sm[64][65];
    const int t = threadIdx.x;
    const int f0 = blockIdx.x * 64;
    const int e  = blockIdx.y;
    const int grp = blockIdx.z;
    const float* W1 = a.W1[grp] + (size_t)e * NF * NH + (size_t)f0 * NH;

    for (int i = t; i < 4096; i += 256) {
        const int fl = i >> 6, h = i & 63;
        sm[fl][h] = W1[(size_t)fl * 64 + h];
    }
    __syncthreads();
    uint32_t* dst = (uint32_t*)g_w1h;
    for (int i = t; i < 2048; i += 256) {
        const int nl = i >> 5, p = i & 31;
        dst[((size_t)grp * 256 + e * 64 + nl) * (NF / 2) + (f0 >> 1) + p] =
            h2pack(sm[2 * p][nl], sm[2 * p + 1][nl]);
    }
}

// ---------------------------------------------------------------------------
// Kernel 0c: W2 [E,H=64,D=256] -> g_w2h [e][n=d][k=h] fp16 (smem transpose)
// ---------------------------------------------------------------------------
struct T2Args { const float* W2[3]; };

__global__ __launch_bounds__(256) void convw2_kernel(T2Args a) {
    __shared__ float sm[64][65];
    const int t = threadIdx.x;
    const int n0t = blockIdx.x * 64;
    const int el  = blockIdx.y;
    const int grp = blockIdx.z;
    const float* W2 = a.W2[grp] + (size_t)el * NH * ND;

    for (int i = t; i < 4096; i += 256) {
        const int k = i >> 6, nl = i & 63;
        sm[k][nl] = W2[(size_t)k * ND + n0t + nl];
    }
    __syncthreads();
    uint32_t* dst = (uint32_t*)g_w2h;
    for (int i = t; i < 2048; i += 256) {
        const int nl = i >> 5, p = i & 31;   // p: k-pair 0..31
        dst[((size_t)(grp * 4 + el) * 256 + n0t + nl) * 32 + p] =
            h2pack(sm[2 * p][nl], sm[2 * p + 1][nl]);
    }
}

// ---------------------------------------------------------------------------
// Kernel 0d: Wg [F,G] -> g_wgh [grp][n=32pad][f] fp16 (pad n>=G with 0)
// grid = 32 (one n-row per block)
// ---------------------------------------------------------------------------
__global__ __launch_bounds__(256) void convg_kernel(const float* __restrict__ Wg,
                                                    int G, int grp) {
    const int nl = blockIdx.x;
    __half* dst = g_wgh + ((size_t)grp * 32 + nl) * NF;
    for (int f = threadIdx.x; f < NF; f += 256)
        dst[f] = (nl < G) ? __float2half(Wg[(size_t)f * G + nl]) : __half(0.f);
}

// ---------------------------------------------------------------------------
// Kernel 1: layer-1 GEMM. fp16 HMMA + cp.async 3-stage + ldmatrix.
// CTA tile 128x256 (FULL N), K-chunk 32. 8 warps 4(m)x2(n), warp 32x128.
// Stage = A[128][80] + B[256][80] = 30720 B; 3 stages = 92160 B (2 CTA/SM).
// ---------------------------------------------------------------------------
struct G1Args { const float* b1[3]; };

#define G1_STG  30720
#define G1_SMEM (3 * G1_STG)

__global__ __launch_bounds__(256) void gemm1_kernel(G1Args args) {
    __shared__ float bias_s[256];
    const uint32_t sb = smem_to_u32(dynsm);

    const int t = threadIdx.x, lane = t & 31, w = t >> 5;
    const int wm = w >> 1, wn = w & 1;
    const int g = lane >> 2, tt = lane & 3;
    const int row0 = blockIdx.x * 128;
    const int grp  = blockIdx.y;

    bias_s[t] = args.b1[grp][t];

    // staging: t<128 -> A row t (4 cp); t>=128 -> B rows u, u+128 (8 cp)
    const bool isA = t < 128;
    const int u = t & 127;
    const __half* gsrcA = g_xh  + ((size_t)grp * NB  + row0 + u) * NF;
    const __half* gsrcB = g_w1h + ((size_t)grp * 256 + u) * NF;      // + u+128 row too
    const uint32_t sdA = sb + (uint32_t)u * 80u;
    const uint32_t sdB = sb + 10240u + (uint32_t)u * 80u;            // +128*80 for 2nd

    // ldmatrix lane address components
    const int jj = lane >> 3, r8 = lane & 7;
    const uint32_t aoff = (uint32_t)((r8 + (jj & 1) * 8) * 80 + (jj >> 1) * 16)
                          + (uint32_t)(wm * 32) * 80u;
    const uint32_t boff = (uint32_t)((r8 + (jj >> 1) * 8) * 80 + (jj & 1) * 16)
                          + (uint32_t)(wn * 128) * 80u + 10240u;

    float acc[2][16][4];
    #pragma unroll
    for (int ma = 0; ma < 2; ma++)
        #pragma unroll
        for (int na = 0; na < 16; na++)
            #pragma unroll
            for (int i = 0; i < 4; i++) acc[ma][na][i] = 0.f;

    auto issue = [&](int c, int stg) {
        if (isA) {
            const uint32_t d = sdA + (uint32_t)stg * G1_STG;
            const __half* s = gsrcA + c * 32;
            #pragma unroll
            for (int seg = 0; seg < 4; seg++) CP_ASYNC16(d + seg * 16, s + seg * 8);
        } else {
            const uint32_t d = sdB + (uint32_t)stg * G1_STG;
            const __half* s = gsrcB + c * 32;
            #pragma unroll
            for (int seg = 0; seg < 4; seg++) CP_ASYNC16(d + seg * 16, s + seg * 8);
            const uint32_t d2 = d + 128u * 80u;
            const __half* s2 = s + (size_t)128 * NF;
            #pragma unroll
            for (int seg = 0; seg < 4; seg++) CP_ASYNC16(d2 + seg * 16, s2 + seg * 8);
        }
    };

    issue(0, 0); CP_COMMIT();
    issue(1, 1); CP_COMMIT();

    for (int c = 0; c < 32; c++) {
        CP_WAIT1();             // group c complete (<=1 newer pending)
        __syncthreads();        // stage (c+2)%3 (read at c-1) now free
        if (c + 2 < 32) issue(c + 2, (c + 2) % 3);
        CP_COMMIT();            // uniform counting (empty in tail)

        const uint32_t stb = sb + (uint32_t)(c % 3) * G1_STG;
        #pragma unroll
        for (int kh = 0; kh < 2; kh++) {
            uint32_t a[2][4];
            #pragma unroll
            for (int ma = 0; ma < 2; ma++)
                LDSM4(a[ma], stb + aoff + ma * 16 * 80 + kh * 32);
            #pragma unroll
            for (int nt = 0; nt < 8; nt++) {
                uint32_t b[4];
                LDSM4(b, stb + boff + nt * 16 * 80 + kh * 32);
                uint32_t b01[2] = {b[0], b[1]};
                uint32_t b23[2] = {b[2], b[3]};
                MMA_F16(acc[0][nt * 2],     a[0], b01);
                MMA_F16(acc[1][nt * 2],     a[1], b01);
                MMA_F16(acc[0][nt * 2 + 1], a[0], b23);
                MMA_F16(acc[1][nt * 2 + 1], a[1], b23);
            }
        }
    }

    // epilogue: bias + relu, fp16 half2 stores
    uint32_t* hb = (uint32_t*)(g_hidh + (size_t)grp * NB * 256);
    #pragma unroll
    for (int ma = 0; ma < 2; ma++) {
        const int r_ = row0 + wm * 32 + ma * 16 + g;
        #pragma unroll
        for (int na = 0; na < 16; na++) {
            const int colb = wn * 128 + na * 8 + 2 * tt;
            const float bb0 = bias_s[colb];
            const float bb1 = bias_s[colb + 1];
            hb[(size_t)r_ * 128 + colb / 2] =
                h2pack(fmaxf(acc[ma][na][0] + bb0, 0.f),
                       fmaxf(acc[ma][na][1] + bb1, 0.f));
            hb[(size_t)(r_ + 8) * 128 + colb / 2] =
                h2pack(fmaxf(acc[ma][na][2] + bb0, 0.f),
                       fmaxf(acc[ma][na][3] + bb1, 0.f));
        }
    }
}

// ---------------------------------------------------------------------------
// Kernel 2: gates via fp16 HMMA. CTA = 256 rows x 32 cols; 8 warps (32 rows ea).
// cp.async 4-stage; stage = A[256][80] + B[32][80] = 23040 B; 4 st = 92160.
// Softmax epilogue: each row's cols live in one lane-quad -> shfl reduce.
// ---------------------------------------------------------------------------
#define GT_STG  23040
#define GT_SMEM (4 * GT_STG)

template <int G>
__global__ __launch_bounds__(256) void gateh_kernel(const float* __restrict__ bg,
                                                    int grp, int off) {
    __shared__ float bgs[32];
    const uint32_t sb = smem_to_u32(dynsm);

    const int t = threadIdx.x, lane = t & 31, w = t >> 5;
    const int g = lane >> 2, tt = lane & 3;
    const int jj = lane >> 3, r8 = lane & 7;
    const int row0 = blockIdx.x * 256;

    if (t < 32) bgs[t] = (t < G) ? bg[t] : 0.f;

    const __half* gsrcA = g_xh + ((size_t)grp * NB + row0 + t) * NF;
    const __half* gsrcB = g_wgh + ((size_t)grp * 32 + (t & 31)) * NF;
    const uint32_t sdA = sb + (uint32_t)t * 80u;
    const uint32_t sdB = sb + 20480u + (uint32_t)(t & 31) * 80u;

    const uint32_t aoff = (uint32_t)((r8 + (jj & 1) * 8) * 80 + (jj >> 1) * 16)
                          + (uint32_t)(w * 32) * 80u;
    const uint32_t boff = (uint32_t)((r8 + (jj >> 1) * 8) * 80 + (jj & 1) * 16) + 20480u;

    float acc[2][4][4];
    #pragma unroll
    for (int ma = 0; ma < 2; ma++)
        #pragma unroll
        for (int na = 0; na < 4; na++)
            #pragma unroll
            for (int i = 0; i < 4; i++) acc[ma][na][i] = 0.f;

    auto issue = [&](int c, int stg) {
        const uint32_t d = sdA + (uint32_t)stg * GT_STG;
        const __half* s = gsrcA + c * 32;
        #pragma unroll
        for (int seg = 0; seg < 4; seg++) CP_ASYNC16(d + seg * 16, s + seg * 8);
        if (t < 32) {
            const uint32_t d2 = sdB + (uint32_t)stg * GT_STG;
            const __half* s2 = gsrcB + c * 32;
            #pragma unroll
            for (int seg = 0; seg < 4; seg++) CP_ASYNC16(d2 + seg * 16, s2 + seg * 8);
        }
    };

    issue(0, 0); CP_COMMIT();
    issue(1, 1); CP_COMMIT();
    issue(2, 2); CP_COMMIT();

    for (int c = 0; c < 32; c++) {
        CP_WAIT2();
        __syncthreads();
        if (c + 3 < 32) issue(c + 3, (c + 3) & 3);
        CP_COMMIT();

        const uint32_t stb = sb + (uint32_t)(c & 3) * GT_STG;
        #pragma unroll
        for (int kh = 0; kh < 2; kh++) {
            uint32_t a[2][4];
            #pragma unroll
            for (int ma = 0; ma < 2; ma++)
                LDSM4(a[ma], stb + aoff + ma * 16 * 80 + kh * 32);
            #pragma unroll
            for (int nt = 0; nt < 2; nt++) {
                uint32_t b[4];
                LDSM4(b, stb + boff + nt * 16 * 80 + kh * 32);
                uint32_t b01[2] = {b[0], b[1]};
                uint32_t b23[2] = {b[2], b[3]};
                MMA_F16(acc[0][nt * 2],     a[0], b01);
                MMA_F16(acc[1][nt * 2],     a[1], b01);
                MMA_F16(acc[0][nt * 2 + 1], a[0], b23);
                MMA_F16(acc[1][nt * 2 + 1], a[1], b23);
            }
        }
    }

    // softmax epilogue: quad (lanes g*4..g*4+3) holds one row's 32 cols
    #pragma unroll
    for (int ma = 0; ma < 2; ma++) {
        #pragma unroll
        for (int rh = 0; rh < 2; rh++) {
            const int row = row0 + w * 32 + ma * 16 + g + rh * 8;
            float lg[8];
            float mx = -1e30f;
            #pragma unroll
            for (int i = 0; i < 8; i++) {
                const int col = (i >> 1) * 8 + 2 * tt + (i & 1);
                lg[i] = (col < G) ? acc[ma][i >> 1][rh * 2 + (i & 1)] + bgs[col] : -1e30f;
                mx = fmaxf(mx, lg[i]);
            }
            mx = fmaxf(mx, __shfl_xor_sync(0xffffffffu, mx, 1));
            mx = fmaxf(mx, __shfl_xor_sync(0xffffffffu, mx, 2));
            float sum = 0.f;
            #pragma unroll
            for (int i = 0; i < 8; i++) {
                lg[i] = ((i >> 1) * 8 + 2 * tt + (i & 1) < G) ? expf(lg[i] - mx) : 0.f;
                sum += lg[i];
            }
            sum += __shfl_xor_sync(0xffffffffu, sum, 1);
            sum += __shfl_xor_sync(0xffffffffu, sum, 2);
            const float inv = 1.f / sum;
            #pragma unroll
            for (int i = 0; i < 8; i++) {
                const int col = (i >> 1) * 8 + 2 * tt + (i & 1);
                if (col < G) g_gates[(size_t)row * 28 + off + col] = lg[i] * inv;
            }
        }
    }
}

// ---------------------------------------------------------------------------
// Kernel 3: layer-2 + relu + gated combine via fp16 HMMA (verified R12)
// ---------------------------------------------------------------------------
struct CArgs { const float* b2[3]; };

#define CB_WS0 0
#define CB_WS1 36864
#define CB_HS  73728
#define CB_B2  99072
#define CB_GS  111360
#define CB_SMEM 113152

__global__ __launch_bounds__(256) void combine_kernel(CArgs args, float* __restrict__ out) {
    const uint32_t sb = smem_to_u32(dynsm);
    float* b2s = (float*)(dynsm + CB_B2);   // [12][256]
    float* gsh = (float*)(dynsm + CB_GS);   // [16][28]

    const int t = threadIdx.x, lane = t & 31, w = t >> 5;
    const int g = lane >> 2, tt = lane & 3;
    const int jj = lane >> 3, r8 = lane & 7;
    const int row0 = blockIdx.x * 16;

    if (t < 192) {
        const int rowi = t >> 2, q = t & 3;
        const int grp = rowi >> 4, r = rowi & 15;
        const uint32_t d = sb + CB_HS + (uint32_t)rowi * 528u + (uint32_t)q * 128u;
        const __half* s = g_hidh + ((size_t)grp * NB + row0 + r) * 256 + q * 64;
        #pragma unroll
        for (int sg = 0; sg < 8; sg++) CP_ASYNC16(d + sg * 16, s + sg * 8);
    }
    {
        const uint32_t d = sb + CB_WS0 + (uint32_t)t * 144u;
        const __half* s = g_w2h + (size_t)t * 64;
        #pragma unroll
        for (int sg = 0; sg < 8; sg++) CP_ASYNC16(d + sg * 16, s + sg * 8);
    }
    CP_COMMIT();
    {
        const uint32_t d = sb + CB_WS1 + (uint32_t)t * 144u;
        const __half* s = g_w2h + ((size_t)256 + t) * 64;
        #pragma unroll
        for (int sg = 0; sg < 8; sg++) CP_ASYNC16(d + sg * 16, s + sg * 8);
    }
    CP_COMMIT();

    for (int i = t; i < 12 * 256; i += 256) {
        const int e = i >> 8, col = i & 255;
        b2s[i] = args.b2[e >> 2][(e & 3) * 256 + col];
    }
    for (int i = t; i < 16 * 28; i += 256)
        gsh[i] = g_gates[(size_t)(row0 + i / 28) * 28 + (i % 28)];

    CP_WAIT1();
    __syncthreads();

    float oA[2][8], oS[2][8], oB[2][8];
    #pragma unroll
    for (int r = 0; r < 2; r++)
        #pragma unroll
        for (int i = 0; i < 8; i++) { oA[r][i] = 0.f; oS[r][i] = 0.f; oB[r][i] = 0.f; }

    for (int e = 0; e < 12; e++) {
        const uint32_t wsb = sb + ((e & 1) ? CB_WS1 : CB_WS0);
        const uint32_t hsb = sb + CB_HS + (uint32_t)(e >> 2) * 16u * 528u
                             + (uint32_t)(e & 3) * 128u;

        uint32_t a[4][4];
        #pragma unroll
        for (int kk = 0; kk < 4; kk++)
            LDSM4(a[kk], hsb + (uint32_t)((r8 + (jj & 1) * 8) * 528 + (jj >> 1) * 16 + kk * 32));

        float acc[4][4];
        #pragma unroll
        for (int na = 0; na < 4; na++)
            #pragma unroll
            for (int i = 0; i < 4; i++) acc[na][i] = 0.f;

        #pragma unroll
        for (int kk = 0; kk < 4; kk++) {
            #pragma unroll
            for (int nt = 0; nt < 2; nt++) {
                uint32_t b[4];
                LDSM4(b, wsb + (uint32_t)((w * 32 + nt * 16 + r8 + (jj >> 1) * 8) * 144
                                          + (jj & 1) * 16 + kk * 32));
                uint32_t b01[2] = {b[0], b[1]};
                uint32_t b23[2] = {b[2], b[3]};
                MMA_F16(acc[nt * 2],     a[kk], b01);
                MMA_F16(acc[nt * 2 + 1], a[kk], b23);
            }
        }

        const float* g0 = &gsh[g * 28];
        const float* g1 = &gsh[(g + 8) * 28];
        const float cS0 = g0[8 + e], cS1 = g1[8 + e];
        float cA0 = 0.f, cA1 = 0.f, cB0 = 0.f, cB1 = 0.f;
        if (e < 8)       { cA0 = g0[e];      cA1 = g1[e]; }
        if (e >= 8)      { cB0 = g0[12 + e]; cB1 = g1[12 + e]; }
        else if (e >= 4) { cB0 = g0[20 + e]; cB1 = g1[20 + e]; }
        #pragma unroll
        for (int na = 0; na < 4; na++) {
            const int col = w * 32 + na * 8 + 2 * tt;
            const float bb0 = b2s[e * 256 + col], bb1 = b2s[e * 256 + col + 1];
            const float v00 = fmaxf(acc[na][0] + bb0, 0.f);
            const float v01 = fmaxf(acc[na][1] + bb1, 0.f);
            const float v10 = fmaxf(acc[na][2] + bb0, 0.f);
            const float v11 = fmaxf(acc[na][3] + bb1, 0.f);
            oA[0][na * 2] += cA0 * v00; oA[0][na * 2 + 1] += cA0 * v01;
            oA[1][na * 2] += cA1 * v10; oA[1][na * 2 + 1] += cA1 * v11;
            oS[0][na * 2] += cS0 * v00; oS[0][na * 2 + 1] += cS0 * v01;
            oS[1][na * 2] += cS1 * v10; oS[1][na * 2 + 1] += cS1 * v11;
            oB[0][na * 2] += cB0 * v00; oB[0][na * 2 + 1] += cB0 * v01;
            oB[1][na * 2] += cB1 * v10; oB[1][na * 2 + 1] += cB1 * v11;
        }

        __syncthreads();
        if (e + 2 < 12) {
            const uint32_t d = sb + ((e & 1) ? CB_WS1 : CB_WS0) + (uint32_t)t * 144u;
            const __half* s = g_w2h + ((size_t)(e + 2) * 256 + t) * 64;
            #pragma unroll
            for (int sg = 0; sg < 8; sg++) CP_ASYNC16(d + sg * 16, s + sg * 8);
        }
        CP_COMMIT();
        CP_WAIT1();
        __syncthreads();
    }

    #pragma unroll
    for (int r = 0; r < 2; r++) {
        const size_t rowb = (size_t)(row0 + r * 8 + g) * 256;
        #pragma unroll
        for (int na = 0; na < 4; na++) {
            const int col = w * 32 + na * 8 + 2 * tt;
            float2 vA = {oA[r][na * 2], oA[r][na * 2 + 1]};
            float2 vS = {oS[r][na * 2], oS[r][na * 2 + 1]};
            float2 vB = {oB[r][na * 2], oB[r][na * 2 + 1]};
            *(float2*)&out[rowb + col]              = vA;
            *(float2*)&out[(size_t)BD + rowb + col] = vS;
            *(float2*)&out[2ull * BD + rowb + col]  = vB;
        }
    }
}

// ---------------------------------------------------------------------------
// Launcher
// ---------------------------------------------------------------------------
extern "C" void kernel_launch(void* const* d_in, const int* in_sizes, int n_in,
                              void* d_out, int out_size) {
    (void)in_sizes; (void)n_in; (void)out_size;
    const float* x_A = (const float*)d_in[0];
    const float* x_S = (const float*)d_in[1];
    const float* x_B = (const float*)d_in[2];
    const float* W1A = (const float*)d_in[3];
    const float* b1A = (const float*)d_in[4];
    const float* W2A = (const float*)d_in[5];
    const float* b2A = (const float*)d_in[6];
    const float* W1S = (const float*)d_in[7];
    const float* b1S = (const float*)d_in[8];
    const float* W2S = (const float*)d_in[9];
    const float* b2S = (const float*)d_in[10];
    const float* W1B = (const float*)d_in[11];
    const float* b1B = (const float*)d_in[12];
    const float* W2B = (const float*)d_in[13];
    const float* b2B = (const float*)d_in[14];
    const float* WgA = (const float*)d_in[15];
    const float* bgA = (const float*)d_in[16];
    const float* WgB = (const float*)d_in[17];
    const float* bgB = (const float*)d_in[18];
    const float* WgS = (const float*)d_in[19];
    const float* bgS = (const float*)d_in[20];
    float* out = (float*)d_out;

    cudaFuncSetAttribute(gemm1_kernel, cudaFuncAttributeMaxDynamicSharedMemorySize, G1_SMEM);
    cudaFuncSetAttribute(gateh_kernel<8>, cudaFuncAttributeMaxDynamicSharedMemorySize, GT_SMEM);
    cudaFuncSetAttribute(gateh_kernel<12>, cudaFuncAttributeMaxDynamicSharedMemorySize, GT_SMEM);
    cudaFuncSetAttribute(combine_kernel, cudaFuncAttributeMaxDynamicSharedMemorySize, CB_SMEM);

    convx_kernel<<<NB * NF / 8 / 256, 256>>>(x_A, 0);
    convx_kernel<<<NB * NF / 8 / 256, 256>>>(x_S, 1);
    convx_kernel<<<NB * NF / 8 / 256, 256>>>(x_B, 2);
    TArgs ta;
    ta.W1[0] = W1A; ta.W1[1] = W1S; ta.W1[2] = W1B;
    convw_kernel<<<dim3(16, 4, 3), 256>>>(ta);
    T2Args t2;
    t2.W2[0] = W2A; t2.W2[1] = W2S; t2.W2[2] = W2B;
    convw2_kernel<<<dim3(4, 4, 3), 256>>>(t2);
    convg_kernel<<<32, 256>>>(WgA, 8, 0);
    convg_kernel<<<32, 256>>>(WgS, 12, 1);
    convg_kernel<<<32, 256>>>(WgB, 8, 2);

    G1Args g1;
    g1.b1[0] = b1A; g1.b1[1] = b1S; g1.b1[2] = b1B;
    gemm1_kernel<<<dim3(NB / 128, 3), 256, G1_SMEM>>>(g1);

    gateh_kernel<8><<<NB / 256, 256, GT_SMEM>>>(bgA, 0, 0);
    gateh_kernel<12><<<NB / 256, 256, GT_SMEM>>>(bgS, 1, 8);
    gateh_kernel<8><<<NB / 256, 256, GT_SMEM>>>(bgB, 2, 20);

    CArgs c2;
    c2.b2[0] = b2A; c2.b2[1] = b2S; c2.b2[2] = b2B;
    combine_kernel<<<NB / 16, 256, CB_SMEM>>>(c2, out);
}

// round 15
// speedup vs baseline: 2.1425x; 1.1938x over previous
#include <cuda_runtime.h>
#include <cuda_fp16.h>
#include <cstdint>

// Problem dims
#define NB   16384
#define NF   1024
#define NH   64
#define ND   256
#define BD   (NB * ND)

// ---------------------------------------------------------------------------
// Scratch (device globals — no allocations allowed)
// ---------------------------------------------------------------------------
__device__ float  g_gates[(size_t)NB * 28];  // per row: gA[8] | gS[12] | gB[8]
__device__ __half g_xh[3ull * NB * NF];      // x in fp16
__device__ __half g_w1h[3ull * 256 * NF];    // W1 transposed [grp][n=e*64+h][f], fp16
__device__ __half g_hidh[3ull * NB * 256];   // hidden [grp][b][256] fp16, relu'd
__device__ __half g_w2h[12ull * 256 * 64];   // W2 transposed [e][n=d][k=h], fp16
__device__ __half g_wgh[3ull * 32 * NF];     // Wg transposed+padded [grp][n=32][f], fp16

extern __shared__ char dynsm[];

// ---------------------------------------------------------------------------
// Helpers
// ---------------------------------------------------------------------------
__device__ __forceinline__ uint32_t h2pack(float a, float b) {
    __half2 h = __floats2half2_rn(a, b);
    return *(uint32_t*)&h;
}
__device__ __forceinline__ uint32_t smem_to_u32(const void* p) {
    uint32_t a;
    asm("{ .reg .u64 t; cvta.to.shared.u64 t, %1; cvt.u32.u64 %0, t; }" : "=r"(a) : "l"(p));
    return a;
}

// m16n8k16 fp16 MMA, fp32 accumulate (native HMMA, sm_80 PTX)
#define MMA_F16(c, a, b) \
    asm("mma.sync.aligned.m16n8k16.row.col.f32.f16.f16.f32 " \
        "{%0,%1,%2,%3}, {%4,%5,%6,%7}, {%8,%9}, {%0,%1,%2,%3};" \
        : "+f"((c)[0]), "+f"((c)[1]), "+f"((c)[2]), "+f"((c)[3]) \
        : "r"((a)[0]), "r"((a)[1]), "r"((a)[2]), "r"((a)[3]), \
          "r"((b)[0]), "r"((b)[1]))

#define LDSM4(rv, addr) \
    asm volatile("ldmatrix.sync.aligned.m8n8.x4.shared.b16 {%0,%1,%2,%3}, [%4];" \
        : "=r"((rv)[0]), "=r"((rv)[1]), "=r"((rv)[2]), "=r"((rv)[3]) : "r"(addr))

#define CP_ASYNC16(dst, src) \
    asm volatile("cp.async.cg.shared.global [%0], [%1], 16;" :: "r"(dst), "l"(src))
#define CP_COMMIT()  asm volatile("cp.async.commit_group;" ::: "memory")
#define CP_WAIT3()   asm volatile("cp.async.wait_group 3;" ::: "memory")
#define CP_WAIT2()   asm volatile("cp.async.wait_group 2;" ::: "memory")
#define CP_WAIT1()   asm volatile("cp.async.wait_group 1;" ::: "memory")

// ---------------------------------------------------------------------------
// Kernel 0a: convert x -> fp16 (one launch per group)
// ---------------------------------------------------------------------------
__global__ __launch_bounds__(256) void convx_kernel(const float* __restrict__ src, int grp) {
    __half* dst = g_xh + (size_t)grp * NB * NF;
    const size_t i = (size_t)blockIdx.x * 256 + threadIdx.x;   // 8 floats each
    const float4 f0 = ((const float4*)src)[2 * i];
    const float4 f1 = ((const float4*)src)[2 * i + 1];
    uint4 o;
    o.x = h2pack(f0.x, f0.y); o.y = h2pack(f0.z, f0.w);
    o.z = h2pack(f1.x, f1.y); o.w = h2pack(f1.z, f1.w);
    ((uint4*)dst)[i] = o;
}

// ---------------------------------------------------------------------------
// Kernel 0b: W1 [E,F,H] -> g_w1h [grp][n=e*64+h][f] fp16 (smem transpose)
// ---------------------------------------------------------------------------
struct TArgs { const float* W1[3]; };

__global__ __launch_bounds__(256) void convw_kernel(TArgs a) {
    __shared__ float sm[64][65];
    const int t = threadIdx.x;
    const int f0 = blockIdx.x * 64;
    const int e  = blockIdx.y;
    const int grp = blockIdx.z;
    const float* W1 = a.W1[grp] + (size_t)e * NF * NH + (size_t)f0 * NH;

    for (int i = t; i < 4096; i += 256) {
        const int fl = i >> 6, h = i & 63;
        sm[fl][h] = W1[(size_t)fl * 64 + h];
    }
    __syncthreads();
    uint32_t* dst = (uint32_t*)g_w1h;
    for (int i = t; i < 2048; i += 256) {
        const int nl = i >> 5, p = i & 31;
        dst[((size_t)grp * 256 + e * 64 + nl) * (NF / 2) + (f0 >> 1) + p] =
            h2pack(sm[2 * p][nl], sm[2 * p + 1][nl]);
    }
}

// ---------------------------------------------------------------------------
// Kernel 0c: W2 [E,H=64,D=256] -> g_w2h [e][n=d][k=h] fp16 (smem transpose)
// ---------------------------------------------------------------------------
struct T2Args { const float* W2[3]; };

__global__ __launch_bounds__(256) void convw2_kernel(T2Args a) {
    __shared__ float sm[64][65];
    const int t = threadIdx.x;
    const int n0t = blockIdx.x * 64;
    const int el  = blockIdx.y;
    const int grp = blockIdx.z;
    const float* W2 = a.W2[grp] + (size_t)el * NH * ND;

    for (int i = t; i < 4096; i += 256) {
        const int k = i >> 6, nl = i & 63;
        sm[k][nl] = W2[(size_t)k * ND + n0t + nl];
    }
    __syncthreads();
    uint32_t* dst = (uint32_t*)g_w2h;
    for (int i = t; i < 2048; i += 256) {
        const int nl = i >> 5, p = i & 31;   // p: k-pair 0..31
        dst[((size_t)(grp * 4 + el) * 256 + n0t + nl) * 32 + p] =
            h2pack(sm[2 * p][nl], sm[2 * p + 1][nl]);
    }
}

// ---------------------------------------------------------------------------
// Kernel 0d: Wg [F,G] -> g_wgh [grp][n=32pad][f] fp16 (pad n>=G with 0)
// ---------------------------------------------------------------------------
__global__ __launch_bounds__(256) void convg_kernel(const float* __restrict__ Wg,
                                                    int G, int grp) {
    const int nl = blockIdx.x;
    __half* dst = g_wgh + ((size_t)grp * 32 + nl) * NF;
    for (int f = threadIdx.x; f < NF; f += 256)
        dst[f] = (nl < G) ? __float2half(Wg[(size_t)f * G + nl]) : __half(0.f);
}

// ---------------------------------------------------------------------------
// Kernel 1: layer-1 GEMM (R12-verified config). fp16 HMMA + cp.async 5-stage
// + ldmatrix. CTA tile 128x128, K-chunk 32. 8 warps 4(m)x2(n), warp 32x64.
// Stage = A[128][80] + B[128][80] = 20480 B; 5 stages = 102400 B dynamic.
// ---------------------------------------------------------------------------
struct G1Args { const float* b1[3]; };

#define STG_BYTES 20480
#define G1_SMEM   (5 * STG_BYTES)

__global__ __launch_bounds__(256) void gemm1_kernel(G1Args args) {
    __shared__ float bias_s[256];
    const uint32_t sb = smem_to_u32(dynsm);

    const int t = threadIdx.x, lane = t & 31, w = t >> 5;
    const int wm = w >> 1, wn = w & 1;
    const int g = lane >> 2, tt = lane & 3;
    const int row0 = blockIdx.x * 128;
    const int n0   = blockIdx.y * 128;
    const int grp  = blockIdx.z;

    bias_s[t] = args.b1[grp][t];

    const bool isA = t < 128;
    const int rr = isA ? t : (t - 128);
    const __half* gsrc = isA
        ? (g_xh  + ((size_t)grp * NB  + row0 + rr) * NF)
        : (g_w1h + ((size_t)grp * 256 + n0   + rr) * NF);
    const uint32_t sdst = sb + (isA ? 0u : 10240u) + (uint32_t)rr * 80u;

    const int jj = lane >> 3, r8 = lane & 7;
    const uint32_t aoff = (uint32_t)((r8 + (jj & 1) * 8) * 80 + (jj >> 1) * 16)
                          + (uint32_t)(wm * 32) * 80u;
    const uint32_t boff = (uint32_t)((r8 + (jj >> 1) * 8) * 80 + (jj & 1) * 16)
                          + (uint32_t)(wn * 64) * 80u + 10240u;

    float acc[2][8][4];
    #pragma unroll
    for (int ma = 0; ma < 2; ma++)
        #pragma unroll
        for (int na = 0; na < 8; na++)
            #pragma unroll
            for (int i = 0; i < 4; i++) acc[ma][na][i] = 0.f;

    auto issue = [&](int c, int stg) {
        const uint32_t d = sdst + (uint32_t)stg * STG_BYTES;
        const __half* s = gsrc + c * 32;
        #pragma unroll
        for (int seg = 0; seg < 4; seg++)
            CP_ASYNC16(d + seg * 16, s + seg * 8);
    };

    issue(0, 0); CP_COMMIT();
    issue(1, 1); CP_COMMIT();
    issue(2, 2); CP_COMMIT();
    issue(3, 3); CP_COMMIT();

    int scur = 0, snew = 4;
    for (int c = 0; c < 32; c++) {
        CP_WAIT3();
        __syncthreads();
        if (c + 4 < 32) issue(c + 4, snew);
        CP_COMMIT();

        const uint32_t stb = sb + (uint32_t)scur * STG_BYTES;
        #pragma unroll
        for (int kh = 0; kh < 2; kh++) {
            uint32_t a[2][4];
            #pragma unroll
            for (int ma = 0; ma < 2; ma++)
                LDSM4(a[ma], stb + aoff + ma * 16 * 80 + kh * 32);
            #pragma unroll
            for (int nt = 0; nt < 4; nt++) {
                uint32_t b[4];
                LDSM4(b, stb + boff + nt * 16 * 80 + kh * 32);
                uint32_t b01[2] = {b[0], b[1]};
                uint32_t b23[2] = {b[2], b[3]};
                MMA_F16(acc[0][nt * 2],     a[0], b01);
                MMA_F16(acc[1][nt * 2],     a[1], b01);
                MMA_F16(acc[0][nt * 2 + 1], a[0], b23);
                MMA_F16(acc[1][nt * 2 + 1], a[1], b23);
            }
        }
        snew = scur;
        scur = (scur == 4) ? 0 : scur + 1;
    }

    uint32_t* hb = (uint32_t*)(g_hidh + (size_t)grp * NB * 256);
    #pragma unroll
    for (int ma = 0; ma < 2; ma++) {
        const int r_ = row0 + wm * 32 + ma * 16 + g;
        #pragma unroll
        for (int na = 0; na < 8; na++) {
            const int colb = wn * 64 + na * 8 + 2 * tt;
            const float bb0 = bias_s[n0 + colb];
            const float bb1 = bias_s[n0 + colb + 1];
            hb[(size_t)r_ * 128 + (n0 + colb) / 2] =
                h2pack(fmaxf(acc[ma][na][0] + bb0, 0.f),
                       fmaxf(acc[ma][na][1] + bb1, 0.f));
            hb[(size_t)(r_ + 8) * 128 + (n0 + colb) / 2] =
                h2pack(fmaxf(acc[ma][na][2] + bb0, 0.f),
                       fmaxf(acc[ma][na][3] + bb1, 0.f));
        }
    }
}

// ---------------------------------------------------------------------------
// Kernel 2: gates via fp16 HMMA (verified R13)
// ---------------------------------------------------------------------------
#define GT_STG  23040
#define GT_SMEM (4 * GT_STG)

template <int G>
__global__ __launch_bounds__(256) void gateh_kernel(const float* __restrict__ bg,
                                                    int grp, int off) {
    __shared__ float bgs[32];
    const uint32_t sb = smem_to_u32(dynsm);

    const int t = threadIdx.x, lane = t & 31, w = t >> 5;
    const int g = lane >> 2, tt = lane & 3;
    const int jj = lane >> 3, r8 = lane & 7;
    const int row0 = blockIdx.x * 256;

    if (t < 32) bgs[t] = (t < G) ? bg[t] : 0.f;

    const __half* gsrcA = g_xh + ((size_t)grp * NB + row0 + t) * NF;
    const __half* gsrcB = g_wgh + ((size_t)grp * 32 + (t & 31)) * NF;
    const uint32_t sdA = sb + (uint32_t)t * 80u;
    const uint32_t sdB = sb + 20480u + (uint32_t)(t & 31) * 80u;

    const uint32_t aoff = (uint32_t)((r8 + (jj & 1) * 8) * 80 + (jj >> 1) * 16)
                          + (uint32_t)(w * 32) * 80u;
    const uint32_t boff = (uint32_t)((r8 + (jj >> 1) * 8) * 80 + (jj & 1) * 16) + 20480u;

    float acc[2][4][4];
    #pragma unroll
    for (int ma = 0; ma < 2; ma++)
        #pragma unroll
        for (int na = 0; na < 4; na++)
            #pragma unroll
            for (int i = 0; i < 4; i++) acc[ma][na][i] = 0.f;

    auto issue = [&](int c, int stg) {
        const uint32_t d = sdA + (uint32_t)stg * GT_STG;
        const __half* s = gsrcA + c * 32;
        #pragma unroll
        for (int seg = 0; seg < 4; seg++) CP_ASYNC16(d + seg * 16, s + seg * 8);
        if (t < 32) {
            const uint32_t d2 = sdB + (uint32_t)stg * GT_STG;
            const __half* s2 = gsrcB + c * 32;
            #pragma unroll
            for (int seg = 0; seg < 4; seg++) CP_ASYNC16(d2 + seg * 16, s2 + seg * 8);
        }
    };

    issue(0, 0); CP_COMMIT();
    issue(1, 1); CP_COMMIT();
    issue(2, 2); CP_COMMIT();

    for (int c = 0; c < 32; c++) {
        CP_WAIT2();
        __syncthreads();
        if (c + 3 < 32) issue(c + 3, (c + 3) & 3);
        CP_COMMIT();

        const uint32_t stb = sb + (uint32_t)(c & 3) * GT_STG;
        #pragma unroll
        for (int kh = 0; kh < 2; kh++) {
            uint32_t a[2][4];
            #pragma unroll
            for (int ma = 0; ma < 2; ma++)
                LDSM4(a[ma], stb + aoff + ma * 16 * 80 + kh * 32);
            #pragma unroll
            for (int nt = 0; nt < 2; nt++) {
                uint32_t b[4];
                LDSM4(b, stb + boff + nt * 16 * 80 + kh * 32);
                uint32_t b01[2] = {b[0], b[1]};
                uint32_t b23[2] = {b[2], b[3]};
                MMA_F16(acc[0][nt * 2],     a[0], b01);
                MMA_F16(acc[1][nt * 2],     a[1], b01);
                MMA_F16(acc[0][nt * 2 + 1], a[0], b23);
                MMA_F16(acc[1][nt * 2 + 1], a[1], b23);
            }
        }
    }

    #pragma unroll
    for (int ma = 0; ma < 2; ma++) {
        #pragma unroll
        for (int rh = 0; rh < 2; rh++) {
            const int row = row0 + w * 32 + ma * 16 + g + rh * 8;
            float lg[8];
            float mx = -1e30f;
            #pragma unroll
            for (int i = 0; i < 8; i++) {
                const int col = (i >> 1) * 8 + 2 * tt + (i & 1);
                lg[i] = (col < G) ? acc[ma][i >> 1][rh * 2 + (i & 1)] + bgs[col] : -1e30f;
                mx = fmaxf(mx, lg[i]);
            }
            mx = fmaxf(mx, __shfl_xor_sync(0xffffffffu, mx, 1));
            mx = fmaxf(mx, __shfl_xor_sync(0xffffffffu, mx, 2));
            float sum = 0.f;
            #pragma unroll
            for (int i = 0; i < 8; i++) {
                lg[i] = ((i >> 1) * 8 + 2 * tt + (i & 1) < G) ? expf(lg[i] - mx) : 0.f;
                sum += lg[i];
            }
            sum += __shfl_xor_sync(0xffffffffu, sum, 1);
            sum += __shfl_xor_sync(0xffffffffu, sum, 2);
            const float inv = 1.f / sum;
            #pragma unroll
            for (int i = 0; i < 8; i++) {
                const int col = (i >> 1) * 8 + 2 * tt + (i & 1);
                if (col < G) g_gates[(size_t)row * 28 + off + col] = lg[i] * inv;
            }
        }
    }
}

// ---------------------------------------------------------------------------
// Kernel 3: layer-2 + relu + gated combine via fp16 HMMA.
// 32 rows/CTA, 512 threads = 16 warps as 2(m-group of 16 rows) x 8(n-warp of
// 32 cols). W2 double-buffered cp.async (protocol identical to verified R12);
// per-warp fragment mapping identical — only row base adds mg*16.
// Smem: Ws[2][256][72h] | Hs[3][32][264h] | b2s[12][256]f | gsh[32][28]f
// ---------------------------------------------------------------------------
struct CArgs { const float* b2[3]; };

#define CB_WS0 0
#define CB_WS1 36864
#define CB_HS  73728
#define CB_B2  (73728 + 50688)              // 124416
#define CB_GS  (124416 + 12288)             // 136704
#define CB_SMEM (136704 + 3584)             // 140288

__global__ __launch_bounds__(512) void combine_kernel(CArgs args, float* __restrict__ out) {
    const uint32_t sb = smem_to_u32(dynsm);
    float* b2s = (float*)(dynsm + CB_B2);   // [12][256]
    float* gsh = (float*)(dynsm + CB_GS);   // [32][28]

    const int t = threadIdx.x, lane = t & 31, w = t >> 5;
    const int mg = w >> 3, wn = w & 7;
    const int g = lane >> 2, tt = lane & 3;
    const int jj = lane >> 3, r8 = lane & 7;
    const int row0 = blockIdx.x * 32;

    // stage Hs: 96 rows (3 grp x 32), 512B each; threads 0..383, quarter each
    if (t < 384) {
        const int rowi = t >> 2, q = t & 3;          // rowi = grp*32 + r
        const int grp = rowi >> 5, r = rowi & 31;
        const uint32_t d = sb + CB_HS + (uint32_t)rowi * 528u + (uint32_t)q * 128u;
        const __half* s = g_hidh + ((size_t)grp * NB + row0 + r) * 256 + q * 64;
        #pragma unroll
        for (int sg = 0; sg < 8; sg++) CP_ASYNC16(d + sg * 16, s + sg * 8);
    }
    // stage W2[0]: 512 threads, half-row each
    {
        const uint32_t d = sb + CB_WS0 + (uint32_t)(t >> 1) * 144u + (uint32_t)(t & 1) * 64u;
        const __half* s = g_w2h + (size_t)(t >> 1) * 64 + (t & 1) * 32;
        #pragma unroll
        for (int sg = 0; sg < 4; sg++) CP_ASYNC16(d + sg * 16, s + sg * 8);
    }
    CP_COMMIT();   // group 0: Hs + W2[0]
    // stage W2[1]
    {
        const uint32_t d = sb + CB_WS1 + (uint32_t)(t >> 1) * 144u + (uint32_t)(t & 1) * 64u;
        const __half* s = g_w2h + ((size_t)256 + (t >> 1)) * 64 + (t & 1) * 32;
        #pragma unroll
        for (int sg = 0; sg < 4; sg++) CP_ASYNC16(d + sg * 16, s + sg * 8);
    }
    CP_COMMIT();   // group 1: W2[1]

    for (int i = t; i < 12 * 256; i += 512) {
        const int e = i >> 8, col = i & 255;
        b2s[i] = args.b2[e >> 2][(e & 3) * 256 + col];
    }
    for (int i = t; i < 32 * 28; i += 512)
        gsh[i] = g_gates[(size_t)(row0 + i / 28) * 28 + (i % 28)];

    CP_WAIT1();
    __syncthreads();

    float oA[2][8], oS[2][8], oB[2][8];
    #pragma unroll
    for (int r = 0; r < 2; r++)
        #pragma unroll
        for (int i = 0; i < 8; i++) { oA[r][i] = 0.f; oS[r][i] = 0.f; oB[r][i] = 0.f; }

    for (int e = 0; e < 12; e++) {
        const uint32_t wsb = sb + ((e & 1) ? CB_WS1 : CB_WS0);
        const uint32_t hsb = sb + CB_HS + (uint32_t)(e >> 2) * 32u * 528u
                             + (uint32_t)mg * 16u * 528u + (uint32_t)(e & 3) * 128u;

        uint32_t a[4][4];
        #pragma unroll
        for (int kk = 0; kk < 4; kk++)
            LDSM4(a[kk], hsb + (uint32_t)((r8 + (jj & 1) * 8) * 528 + (jj >> 1) * 16 + kk * 32));

        float acc[4][4];
        #pragma unroll
        for (int na = 0; na < 4; na++)
            #pragma unroll
            for (int i = 0; i < 4; i++) acc[na][i] = 0.f;

        #pragma unroll
        for (int kk = 0; kk < 4; kk++) {
            #pragma unroll
            for (int nt = 0; nt < 2; nt++) {
                uint32_t b[4];
                LDSM4(b, wsb + (uint32_t)((wn * 32 + nt * 16 + r8 + (jj >> 1) * 8) * 144
                                          + (jj & 1) * 16 + kk * 32));
                uint32_t b01[2] = {b[0], b[1]};
                uint32_t b23[2] = {b[2], b[3]};
                MMA_F16(acc[nt * 2],     a[kk], b01);
                MMA_F16(acc[nt * 2 + 1], a[kk], b23);
            }
        }

        const float* g0 = &gsh[(mg * 16 + g) * 28];
        const float* g1 = &gsh[(mg * 16 + g + 8) * 28];
        const float cS0 = g0[8 + e], cS1 = g1[8 + e];
        float cA0 = 0.f, cA1 = 0.f, cB0 = 0.f, cB1 = 0.f;
        if (e < 8)       { cA0 = g0[e];      cA1 = g1[e]; }
        if (e >= 8)      { cB0 = g0[12 + e]; cB1 = g1[12 + e]; }
        else if (e >= 4) { cB0 = g0[20 + e]; cB1 = g1[20 + e]; }
        #pragma unroll
        for (int na = 0; na < 4; na++) {
            const int col = wn * 32 + na * 8 + 2 * tt;
            const float bb0 = b2s[e * 256 + col], bb1 = b2s[e * 256 + col + 1];
            const float v00 = fmaxf(acc[na][0] + bb0, 0.f);
            const float v01 = fmaxf(acc[na][1] + bb1, 0.f);
            const float v10 = fmaxf(acc[na][2] + bb0, 0.f);
            const float v11 = fmaxf(acc[na][3] + bb1, 0.f);
            oA[0][na * 2] += cA0 * v00; oA[0][na * 2 + 1] += cA0 * v01;
            oA[1][na * 2] += cA1 * v10; oA[1][na * 2 + 1] += cA1 * v11;
            oS[0][na * 2] += cS0 * v00; oS[0][na * 2 + 1] += cS0 * v01;
            oS[1][na * 2] += cS1 * v10; oS[1][na * 2 + 1] += cS1 * v11;
            oB[0][na * 2] += cB0 * v00; oB[0][na * 2 + 1] += cB0 * v01;
            oB[1][na * 2] += cB1 * v10; oB[1][na * 2 + 1] += cB1 * v11;
        }

        __syncthreads();                       // all warps done reading Ws[e&1]
        if (e + 2 < 12) {
            const uint32_t d = sb + ((e & 1) ? CB_WS1 : CB_WS0)
                               + (uint32_t)(t >> 1) * 144u + (uint32_t)(t & 1) * 64u;
            const __half* s = g_w2h + ((size_t)(e + 2) * 256 + (t >> 1)) * 64 + (t & 1) * 32;
            #pragma unroll
            for (int sg = 0; sg < 4; sg++) CP_ASYNC16(d + sg * 16, s + sg * 8);
        }
        CP_COMMIT();
        CP_WAIT1();                            // W2[e+1] complete
        __syncthreads();
    }

    #pragma unroll
    for (int r = 0; r < 2; r++) {
        const size_t rowb = (size_t)(row0 + mg * 16 + r * 8 + g) * 256;
        #pragma unroll
        for (int na = 0; na < 4; na++) {
            const int col = wn * 32 + na * 8 + 2 * tt;
            float2 vA = {oA[r][na * 2], oA[r][na * 2 + 1]};
            float2 vS = {oS[r][na * 2], oS[r][na * 2 + 1]};
            float2 vB = {oB[r][na * 2], oB[r][na * 2 + 1]};
            *(float2*)&out[rowb + col]              = vA;
            *(float2*)&out[(size_t)BD + rowb + col] = vS;
            *(float2*)&out[2ull * BD + rowb + col]  = vB;
        }
    }
}

// ---------------------------------------------------------------------------
// Launcher
// ---------------------------------------------------------------------------
extern "C" void kernel_launch(void* const* d_in, const int* in_sizes, int n_in,
                              void* d_out, int out_size) {
    (void)in_sizes; (void)n_in; (void)out_size;
    const float* x_A = (const float*)d_in[0];
    const float* x_S = (const float*)d_in[1];
    const float* x_B = (const float*)d_in[2];
    const float* W1A = (const float*)d_in[3];
    const float* b1A = (const float*)d_in[4];
    const float* W2A = (const float*)d_in[5];
    const float* b2A = (const float*)d_in[6];
    const float* W1S = (const float*)d_in[7];
    const float* b1S = (const float*)d_in[8];
    const float* W2S = (const float*)d_in[9];
    const float* b2S = (const float*)d_in[10];
    const float* W1B = (const float*)d_in[11];
    const float* b1B = (const float*)d_in[12];
    const float* W2B = (const float*)d_in[13];
    const float* b2B = (const float*)d_in[14];
    const float* WgA = (const float*)d_in[15];
    const float* bgA = (const float*)d_in[16];
    const float* WgB = (const float*)d_in[17];
    const float* bgB = (const float*)d_in[18];
    const float* WgS = (const float*)d_in[19];
    const float* bgS = (const float*)d_in[20];
    float* out = (float*)d_out;

    cudaFuncSetAttribute(gemm1_kernel, cudaFuncAttributeMaxDynamicSharedMemorySize, G1_SMEM);
    cudaFuncSetAttribute(gateh_kernel<8>, cudaFuncAttributeMaxDynamicSharedMemorySize, GT_SMEM);
    cudaFuncSetAttribute(gateh_kernel<12>, cudaFuncAttributeMaxDynamicSharedMemorySize, GT_SMEM);
    cudaFuncSetAttribute(combine_kernel, cudaFuncAttributeMaxDynamicSharedMemorySize, CB_SMEM);

    convx_kernel<<<NB * NF / 8 / 256, 256>>>(x_A, 0);
    convx_kernel<<<NB * NF / 8 / 256, 256>>>(x_S, 1);
    convx_kernel<<<NB * NF / 8 / 256, 256>>>(x_B, 2);
    TArgs ta;
    ta.W1[0] = W1A; ta.W1[1] = W1S; ta.W1[2] = W1B;
    convw_kernel<<<dim3(16, 4, 3), 256>>>(ta);
    T2Args t2;
    t2.W2[0] = W2A; t2.W2[1] = W2S; t2.W2[2] = W2B;
    convw2_kernel<<<dim3(4, 4, 3), 256>>>(t2);
    convg_kernel<<<32, 256>>>(WgA, 8, 0);
    convg_kernel<<<32, 256>>>(WgS, 12, 1);
    convg_kernel<<<32, 256>>>(WgB, 8, 2);

    G1Args g1;
    g1.b1[0] = b1A; g1.b1[1] = b1S; g1.b1[2] = b1B;
    gemm1_kernel<<<dim3(NB / 128, 2, 3), 256, G1_SMEM>>>(g1);

    gateh_kernel<8><<<NB / 256, 256, GT_SMEM>>>(bgA, 0, 0);
    gateh_kernel<12><<<NB / 256, 256, GT_SMEM>>>(bgS, 1, 8);
    gateh_kernel<8><<<NB / 256, 256, GT_SMEM>>>(bgB, 2, 20);

    CArgs c2;
    c2.b2[0] = b2A; c2.b2[1] = b2S; c2.b2[2] = b2B;
    combine_kernel<<<NB / 32, 512, CB_SMEM>>>(c2, out);
}